// round 11
// baseline (speedup 1.0000x reference)
#include <cuda_runtime.h>
#include <cuda_bf16.h>
#include <cstdint>
#include <cstddef>

#define NN 50000
#define NE 800000
#define D  128
#define NL 5
#define BN_EPS 1e-3f
#define NTILES ((NN + 127) / 128)   // 391

// ---------------- scratch (no allocs allowed) ----------------
__device__ __nv_bfloat16 g_wb[NL * 4 * 16384];   // W1h W1l W2h W2l per layer
__device__ int g_off[NN + 1];
__device__ int g_cur[NN];
__device__ int g_csr[NE];
#define SCAN_BLK 1024
#define SCAN_NB  ((NN + SCAN_BLK - 1) / SCAN_BLK)   // 49
__device__ int g_bsum[SCAN_NB];

// ---------------- helpers ----------------
__device__ __forceinline__ uint32_t smem_u32(const void* p) {
    uint32_t a;
    asm("{ .reg .u64 t; cvta.to.shared.u64 t, %1; cvt.u32.u64 %0, t; }" : "=r"(a) : "l"(p));
    return a;
}
__device__ __forceinline__ void split_bf(float v, uint16_t& h, uint16_t& l) {
    __nv_bfloat16 hb = __float2bfloat16_rn(v);
    float rem = v - __bfloat162float(hb);
    h = __bfloat16_as_ushort(hb);
    l = __bfloat16_as_ushort(__float2bfloat16_rn(rem));
}
// truncation split of a float pair: hi = top16 bits of each, lo = rn-bf16 of remainders
__device__ __forceinline__ void split2(float x, float y, uint32_t& hi, uint32_t& lo) {
    uint32_t xi = __float_as_uint(x), yi = __float_as_uint(y);
    hi = __byte_perm(xi, yi, 0x7632);
    float xr = x - __uint_as_float(xi & 0xFFFF0000u);
    float yr = y - __uint_as_float(yi & 0xFFFF0000u);
    asm("cvt.rn.bf16x2.f32 %0, %1, %2;" : "=r"(lo) : "f"(yr), "f"(xr));
}
__device__ __forceinline__ void ldm_x4(uint32_t (&r)[4], uint32_t addr) {
    asm volatile("ldmatrix.sync.aligned.m8n8.x4.shared.b16 {%0,%1,%2,%3}, [%4];"
                 : "=r"(r[0]), "=r"(r[1]), "=r"(r[2]), "=r"(r[3]) : "r"(addr));
}
__device__ __forceinline__ void ldm_x4t(uint32_t (&r)[4], uint32_t addr) {
    asm volatile("ldmatrix.sync.aligned.m8n8.x4.trans.shared.b16 {%0,%1,%2,%3}, [%4];"
                 : "=r"(r[0]), "=r"(r[1]), "=r"(r[2]), "=r"(r[3]) : "r"(addr));
}
__device__ __forceinline__ void mma_bf16(float (&d)[4], const uint32_t (&a)[4],
                                         uint32_t b0, uint32_t b1) {
    asm volatile("mma.sync.aligned.m16n8k16.row.col.f32.bf16.bf16.f32 "
                 "{%0,%1,%2,%3}, {%4,%5,%6,%7}, {%8,%9}, {%0,%1,%2,%3};"
                 : "+f"(d[0]), "+f"(d[1]), "+f"(d[2]), "+f"(d[3])
                 : "r"(a[0]), "r"(a[1]), "r"(a[2]), "r"(a[3]), "r"(b0), "r"(b1));
}
#define PBAR(id) asm volatile("bar.sync %0, 64;" :: "r"((id) + 1) : "memory")

// ---------------------------------------------------------------------------
// CSR build (once per launch)
// ---------------------------------------------------------------------------
__global__ void zero_off_k() {
    int i = blockIdx.x * 256 + threadIdx.x;
    if (i <= NN) g_off[i] = 0;
}
__global__ void hist_k(const int* __restrict__ dst) {
    int e = blockIdx.x * 256 + threadIdx.x;
    if (e < NE) atomicAdd(&g_off[__ldg(&dst[e]) + 1], 1);
}
__global__ void scanA_k() {
    __shared__ int wsum[32];
    const int tid  = threadIdx.x;
    const int lane = tid & 31;
    const int wid  = tid >> 5;
    int i = blockIdx.x * SCAN_BLK + tid;
    int c = (i < NN) ? g_off[i + 1] : 0;
    int v = c;
    #pragma unroll
    for (int d = 1; d < 32; d <<= 1) {
        int t = __shfl_up_sync(0xFFFFFFFFu, v, d);
        if (lane >= d) v += t;
    }
    if (lane == 31) wsum[wid] = v;
    __syncthreads();
    if (wid == 0) {
        int w = wsum[lane];
        #pragma unroll
        for (int d = 1; d < 32; d <<= 1) {
            int t = __shfl_up_sync(0xFFFFFFFFu, w, d);
            if (lane >= d) w += t;
        }
        wsum[lane] = w;
    }
    __syncthreads();
    int inc = v + (wid > 0 ? wsum[wid - 1] : 0);
    if (i < NN) {
        g_off[i + 1] = inc;
        g_cur[i] = c;
    }
    if (tid == SCAN_BLK - 1) g_bsum[blockIdx.x] = inc;
}
__global__ void scanB_k() {
    __shared__ int s[64];
    int t = threadIdx.x;
    int v = (t < SCAN_NB) ? g_bsum[t] : 0;
    int lane = t & 31, wid = t >> 5;
    int x = v;
    #pragma unroll
    for (int d = 1; d < 32; d <<= 1) {
        int u = __shfl_up_sync(0xFFFFFFFFu, x, d);
        if (lane >= d) x += u;
    }
    if (lane == 31) s[wid] = x;
    __syncthreads();
    int inc = x + (wid > 0 ? s[0] : 0);
    if (t < SCAN_NB) g_bsum[t] = inc;
}
__global__ void scanC_k() {
    int i = blockIdx.x * SCAN_BLK + threadIdx.x;
    if (i >= NN) return;
    int add = (blockIdx.x > 0) ? g_bsum[blockIdx.x - 1] : 0;
    int inc = g_off[i + 1] + add;
    g_off[i + 1] = inc;
    g_cur[i] = inc - g_cur[i];
}
__global__ void fill_k(const int* __restrict__ src, const int* __restrict__ dst) {
    int e = blockIdx.x * 256 + threadIdx.x;
    if (e >= NE) return;
    int p = atomicAdd(&g_cur[__ldg(&dst[e])], 1);
    g_csr[p] = __ldg(&src[e]);
}

// ---------------------------------------------------------------------------
// Weight prep
// ---------------------------------------------------------------------------
__global__ void prep_w_k(const float* __restrict__ W1, const float* __restrict__ W2) {
    int l   = blockIdx.x >> 1;
    int mat = blockIdx.x & 1;
    const float* W = (mat ? W2 : W1) + (size_t)l * 16384;
    __nv_bfloat16* dh = g_wb + ((size_t)(l * 2 + mat) * 2 + 0) * 16384;
    __nv_bfloat16* dl = g_wb + ((size_t)(l * 2 + mat) * 2 + 1) * 16384;
    for (int i = threadIdx.x; i < 16384; i += 256) {
        uint16_t hb, lb;
        split_bf(__ldg(&W[i]), hb, lb);
        dh[i] = __ushort_as_bfloat16(hb);
        dl[i] = __ushort_as_bfloat16(lb);
    }
}

// ---------------------------------------------------------------------------
// FUSED GIN layer: per tile each warp-pair streams its 32 rows' contiguous
// CSR edge range (csr/offs staged in SMEM), double-buffered 16-deep register
// chunks, flushing (1+eps)*self + sum directly into split bf16 A planes.
// Then the R10 tensor-core MLP (fused 3-term) + BN + ReLU.
// ---------------------------------------------------------------------------
#define LDB     272
#define MATSZ   (128 * LDB)
#define AH_OFF  0
#define AL_OFF  MATSZ
#define W1H_OFF (2 * MATSZ)
#define W1L_OFF (3 * MATSZ)
#define W2H_OFF (4 * MATSZ)
#define W2L_OFF (5 * MATSZ)
#define PB1_OFF (6 * MATSZ)
#define PS_OFF  (PB1_OFF + 512)
#define PT_OFF  (PS_OFF + 512)
#define CSR_OFF (PT_OFF + 512)         // 4 pair regions
#define CSR_CAP 1024
#define CSR_STRIDE 4352                // 1024 csr ints + 33 offs + pad
#define SMEM_REQ (CSR_OFF + 4 * CSR_STRIDE)   // 227840 <= 232448

#define CH 16

__device__ __forceinline__ void gemm_fused(uint32_t sbase,
                                           uint32_t whOff, uint32_t wlOff,
                                           int wm, int wn, int lane,
                                           float acc[2][8][4]) {
    const int lane15 = lane & 15;
    const int lhalf  = (lane >> 4) << 3;
    const uint32_t aRowBase = (uint32_t)(wm * 32 + lane15) * LDB + (uint32_t)lhalf * 2;
    const uint32_t bBaseOff = (uint32_t)lane15 * LDB + (uint32_t)(wn * 64 + lhalf) * 2;
    const uint32_t aH = sbase + AH_OFF + aRowBase;
    const uint32_t aL = sbase + AL_OFF + aRowBase;
    const uint32_t bH = sbase + whOff + bBaseOff;
    const uint32_t bL = sbase + wlOff + bBaseOff;
    #pragma unroll
    for (int ks = 0; ks < 8; ks++) {
        uint32_t aH0[4], aH1[4], aL0[4], aL1[4];
        ldm_x4(aH0, aH + ks * 32);
        ldm_x4(aH1, aH + 16 * LDB + ks * 32);
        ldm_x4(aL0, aL + ks * 32);
        ldm_x4(aL1, aL + 16 * LDB + ks * 32);
        uint32_t bh[4][4], bl[4][4];
        #pragma unroll
        for (int np = 0; np < 4; np++) {
            ldm_x4t(bh[np], bH + (uint32_t)ks * (16 * LDB) + np * 32);
            ldm_x4t(bl[np], bL + (uint32_t)ks * (16 * LDB) + np * 32);
        }
        #pragma unroll
        for (int nt = 0; nt < 8; nt++) {
            uint32_t b0h = bh[nt >> 1][(nt & 1) * 2], b1h = bh[nt >> 1][(nt & 1) * 2 + 1];
            uint32_t b0l = bl[nt >> 1][(nt & 1) * 2], b1l = bl[nt >> 1][(nt & 1) * 2 + 1];
            mma_bf16(acc[0][nt], aH0, b0h, b1h);
            mma_bf16(acc[1][nt], aH1, b0h, b1h);
            mma_bf16(acc[0][nt], aH0, b0l, b1l);
            mma_bf16(acc[1][nt], aH1, b0l, b1l);
            mma_bf16(acc[0][nt], aL0, b0h, b1h);
            mma_bf16(acc[1][nt], aL1, b0h, b1h);
        }
    }
}

// gather pipeline macros (pair-uniform control flow)
#define GISSUE(BUF, BASE) do { \
    _Pragma("unroll") \
    for (int j = 0; j < CH; j++) { \
        int idx = (BASE) + j; \
        if (idx < eTot) { \
            int s = (idx < CSR_CAP) ? smCsr[idx] : __ldg(&g_csr[eBeg + idx]); \
            BUF[j] = __ldg(h2 + (size_t)s * 64 + ptid); \
        } \
    } \
} while (0)

#define GFLUSH() do { \
    uint32_t hv, lv; \
    split2(acc.x, acc.y, hv, lv); \
    uint32_t aoff = (uint32_t)(wm * 32 + rIdx) * LDB + (uint32_t)ptid * 4; \
    *(uint32_t*)(sm + AH_OFF + aoff) = hv; \
    *(uint32_t*)(sm + AL_OFF + aoff) = lv; \
    rIdx++; \
    acc.x = eps1 * selfN.x; acc.y = eps1 * selfN.y; \
    if (rIdx + 1 < nRows) selfN = __ldg(h2 + (size_t)(rowLo + rIdx + 1) * 64 + ptid); \
    endCur = (rIdx < nRows) ? smOff[rIdx + 1] : 0x7FFFFFFF; \
} while (0)

#define GCONSUME(BUF, BASE) do { \
    _Pragma("unroll") \
    for (int j = 0; j < CH; j++) { \
        int idx = (BASE) + j; \
        if (idx < eTot) { \
            while (idx == endCur) GFLUSH(); \
            acc.x += BUF[j].x; acc.y += BUF[j].y; \
        } \
    } \
} while (0)

__global__ void __launch_bounds__(256, 1) gin_fused_k(
    float* __restrict__ out, const float* __restrict__ h, int layer,
    const float* __restrict__ epsArr,
    const float* __restrict__ b1, const float* __restrict__ b2,
    const float* __restrict__ gamma, const float* __restrict__ beta,
    const float* __restrict__ bmean, const float* __restrict__ bvar)
{
    extern __shared__ char sm[];
    const uint32_t sbase = smem_u32(sm);
    const int tid  = threadIdx.x;
    const int wid  = tid >> 5;
    const int lane = tid & 31;
    const int wm   = wid & 3;            // 4 M-groups of 32 rows (pair id)
    const int wn   = wid >> 2;           // 2 N-groups of 64 cols
    const int ptid = (wn << 5) | lane;   // 0..63 within pair

    const float eps1 = 1.0f + __ldg(&epsArr[layer]);
    const float2* h2 = (const float2*)h;

    float* B1f = (float*)(sm + PB1_OFF);
    float* Sf  = (float*)(sm + PS_OFF);
    float* Tf  = (float*)(sm + PT_OFF);
    if (tid < 128) {
        float s = __ldg(&gamma[tid]) * rsqrtf(__ldg(&bvar[tid]) + BN_EPS);
        Sf[tid]  = s;
        Tf[tid]  = __ldg(&b2[tid]) * s + __ldg(&beta[tid]) - __ldg(&bmean[tid]) * s;
        B1f[tid] = __ldg(&b1[tid]);
    }

    {
        const uint4* wsrc = (const uint4*)(g_wb + (size_t)layer * 4 * 16384);
        #pragma unroll
        for (int it = 0; it < 32; it++) {
            int idx = tid + it * 256;
            int mat = idx >> 11;
            int j   = idx & 2047;
            int k   = j >> 4, c = j & 15;
            *(uint4*)(sm + W1H_OFF + mat * MATSZ + k * LDB + c * 16) = __ldg(&wsrc[idx]);
        }
    }
    __syncthreads();

    int* smCsr = (int*)(sm + CSR_OFF + wm * CSR_STRIDE);
    int* smOff = smCsr + CSR_CAP;

    const int rEp = lane >> 2;
    const int cEp = (lane & 3) * 2;

    for (int t = blockIdx.x; t < NTILES; t += gridDim.x) {
        const int rowBase = t * 128;
        const int rowLo = rowBase + wm * 32;
        const int rowHi = (rowLo + 32 < NN) ? rowLo + 32 : NN;
        const int nRows = (rowHi > rowLo) ? rowHi - rowLo : 0;

        // ---- stage csr + offs for this pair ----
        int eBeg = 0, eTot = 0;
        if (nRows > 0) {
            eBeg = __ldg(&g_off[rowLo]);
            eTot = __ldg(&g_off[rowHi]) - eBeg;
            int nld = (eTot < CSR_CAP) ? eTot : CSR_CAP;
            for (int k = ptid; k < nld; k += 64) smCsr[k] = __ldg(&g_csr[eBeg + k]);
            for (int k = ptid; k <= nRows; k += 64) smOff[k] = __ldg(&g_off[rowLo + k]) - eBeg;
        }
        PBAR(wm);

        // ---- streamed gather: (1+eps)*self + neighbor sum -> A planes ----
        if (nRows > 0) {
            float2 acc;
            {
                float2 sv = __ldg(h2 + (size_t)rowLo * 64 + ptid);
                acc.x = eps1 * sv.x; acc.y = eps1 * sv.y;
            }
            float2 selfN = make_float2(0.f, 0.f);
            if (nRows > 1) selfN = __ldg(h2 + (size_t)(rowLo + 1) * 64 + ptid);
            int rIdx = 0;
            int endCur = smOff[1];
            float2 bufA[CH], bufB[CH];

            GISSUE(bufA, 0);
            int base = 0;
            if (eTot > 0) {
                while (true) {
                    GISSUE(bufB, base + CH);
                    GCONSUME(bufA, base);
                    base += CH;
                    if (base >= eTot) break;
                    GISSUE(bufA, base + CH);
                    GCONSUME(bufB, base);
                    base += CH;
                    if (base >= eTot) break;
                }
            }
            while (rIdx < nRows) GFLUSH();
        }
        // zero-fill rows beyond NN
        for (int r = nRows; r < 32; r++) {
            uint32_t aoff = (uint32_t)(wm * 32 + r) * LDB + (uint32_t)ptid * 4;
            *(uint32_t*)(sm + AH_OFF + aoff) = 0;
            *(uint32_t*)(sm + AL_OFF + aoff) = 0;
        }
        PBAR(wm);

        float acc[2][8][4];
        #pragma unroll
        for (int a = 0; a < 2; a++)
            #pragma unroll
            for (int b = 0; b < 8; b++)
                #pragma unroll
                for (int c = 0; c < 4; c++) acc[a][b][c] = 0.f;

        gemm_fused(sbase, W1H_OFF, W1L_OFF, wm, wn, lane, acc);
        PBAR(wm);   // pair done reading A rows

        // ---- epilogue 1: Z = relu(D1 + b1) -> split back into AH/AL ----
        #pragma unroll
        for (int mt = 0; mt < 2; mt++) {
            #pragma unroll
            for (int nt = 0; nt < 8; nt++) {
                int row = wm * 32 + mt * 16 + rEp;
                int col = wn * 64 + nt * 8 + cEp;
                float f0 = fmaxf(acc[mt][nt][0] + B1f[col],     0.f);
                float f1 = fmaxf(acc[mt][nt][1] + B1f[col + 1], 0.f);
                float f2 = fmaxf(acc[mt][nt][2] + B1f[col],     0.f);
                float f3 = fmaxf(acc[mt][nt][3] + B1f[col + 1], 0.f);
                uint32_t h0, l0, h1, l1;
                split2(f0, f1, h0, l0);
                split2(f2, f3, h1, l1);
                uint32_t o0 = (uint32_t)row * LDB + (uint32_t)col * 2;
                uint32_t o1 = o0 + 8 * LDB;
                *(uint32_t*)(sm + AH_OFF + o0) = h0;
                *(uint32_t*)(sm + AL_OFF + o0) = l0;
                *(uint32_t*)(sm + AH_OFF + o1) = h1;
                *(uint32_t*)(sm + AL_OFF + o1) = l1;
            }
        }
        PBAR(wm);

        #pragma unroll
        for (int a = 0; a < 2; a++)
            #pragma unroll
            for (int b = 0; b < 8; b++)
                #pragma unroll
                for (int c = 0; c < 4; c++) acc[a][b][c] = 0.f;

        gemm_fused(sbase, W2H_OFF, W2L_OFF, wm, wn, lane, acc);
        PBAR(wm);   // pair done reading Z before next-tile writes

        // ---- epilogue 2: out = relu(D2 * S + T) ----
        #pragma unroll
        for (int mt = 0; mt < 2; mt++) {
            #pragma unroll
            for (int nt = 0; nt < 8; nt++) {
                int row = wm * 32 + mt * 16 + rEp;
                int col = wn * 64 + nt * 8 + cEp;
                int gr0 = rowBase + row;
                int gr1 = gr0 + 8;
                float2 o0, o1;
                o0.x = fmaxf(fmaf(acc[mt][nt][0], Sf[col],     Tf[col]),     0.f);
                o0.y = fmaxf(fmaf(acc[mt][nt][1], Sf[col + 1], Tf[col + 1]), 0.f);
                o1.x = fmaxf(fmaf(acc[mt][nt][2], Sf[col],     Tf[col]),     0.f);
                o1.y = fmaxf(fmaf(acc[mt][nt][3], Sf[col + 1], Tf[col + 1]), 0.f);
                if (gr0 < NN) *(float2*)(out + (size_t)gr0 * D + col) = o0;
                if (gr1 < NN) *(float2*)(out + (size_t)gr1 * D + col) = o1;
            }
        }
    }
}

// ---------------------------------------------------------------------------
extern "C" void kernel_launch(void* const* d_in, const int* in_sizes, int n_in,
                              void* d_out, int out_size) {
    const float* x     = (const float*)d_in[0];
    const int*   esrc  = (const int*)  d_in[1];
    const int*   edst  = (const int*)  d_in[2];
    const float* eps   = (const float*)d_in[3];
    const float* W1    = (const float*)d_in[4];
    const float* b1    = (const float*)d_in[5];
    const float* W2    = (const float*)d_in[6];
    const float* b2    = (const float*)d_in[7];
    const float* gamma = (const float*)d_in[8];
    const float* beta  = (const float*)d_in[9];
    const float* bmean = (const float*)d_in[10];
    const float* bvar  = (const float*)d_in[11];
    float* out = (float*)d_out;

    static int smem_set = 0;
    if (!smem_set) {
        cudaFuncSetAttribute(gin_fused_k, cudaFuncAttributeMaxDynamicSharedMemorySize, SMEM_REQ);
        smem_set = 1;
    }

    // hidden_rep[0] = x
    cudaMemcpyAsync(out, x, (size_t)NN * D * sizeof(float), cudaMemcpyDeviceToDevice);

    // one-shot: weight split + CSR build
    prep_w_k<<<NL * 2, 256>>>(W1, W2);
    zero_off_k<<<(NN + 256) / 256, 256>>>();
    hist_k<<<(NE + 255) / 256, 256>>>(edst);
    scanA_k<<<SCAN_NB, SCAN_BLK>>>();
    scanB_k<<<1, 64>>>();
    scanC_k<<<SCAN_NB, SCAN_BLK>>>();
    fill_k<<<(NE + 255) / 256, 256>>>(esrc, edst);

    for (int l = 0; l < NL; l++) {
        const float* h  = out + (size_t)l * NN * D;
        float*       hn = out + (size_t)(l + 1) * NN * D;
        gin_fused_k<<<148, 256, SMEM_REQ>>>(hn, h, l, eps,
            b1 + (size_t)l * D, b2 + (size_t)l * D,
            gamma + (size_t)l * D, beta + (size_t)l * D,
            bmean + (size_t)l * D, bvar + (size_t)l * D);
    }
}

// round 12
// speedup vs baseline: 5.7757x; 5.7757x over previous
#include <cuda_runtime.h>
#include <cuda_bf16.h>
#include <cstdint>
#include <cstddef>

#define NN 50000
#define NE 800000
#define D  128
#define NL 5
#define BN_EPS 1e-3f
#define NTILES ((NN + 127) / 128)   // 391

// ---------------- scratch (no allocs allowed) ----------------
__device__ float g_pooled[NN * D];
__device__ __nv_bfloat16 g_wb[NL * 4 * 16384];   // W1h W1l W2h W2l per layer
__device__ int g_off[NN + 1];
__device__ int g_cur[NN];
__device__ int g_csr[NE];
#define SCAN_BLK 1024
#define SCAN_NB  ((NN + SCAN_BLK - 1) / SCAN_BLK)   // 49
__device__ int g_bsum[SCAN_NB];

// ---------------- helpers ----------------
__device__ __forceinline__ uint32_t smem_u32(const void* p) {
    uint32_t a;
    asm("{ .reg .u64 t; cvta.to.shared.u64 t, %1; cvt.u32.u64 %0, t; }" : "=r"(a) : "l"(p));
    return a;
}
__device__ __forceinline__ void split_bf(float v, uint16_t& h, uint16_t& l) {
    __nv_bfloat16 hb = __float2bfloat16_rn(v);
    float rem = v - __bfloat162float(hb);
    h = __bfloat16_as_ushort(hb);
    l = __bfloat16_as_ushort(__float2bfloat16_rn(rem));
}
// truncation split of a float pair: hi = top16 bits of each, lo = rn-bf16 of remainders
__device__ __forceinline__ void split2(float x, float y, uint32_t& hi, uint32_t& lo) {
    uint32_t xi = __float_as_uint(x), yi = __float_as_uint(y);
    hi = __byte_perm(xi, yi, 0x7632);
    float xr = x - __uint_as_float(xi & 0xFFFF0000u);
    float yr = y - __uint_as_float(yi & 0xFFFF0000u);
    asm("cvt.rn.bf16x2.f32 %0, %1, %2;" : "=r"(lo) : "f"(yr), "f"(xr));
}
__device__ __forceinline__ void ldm_x4(uint32_t (&r)[4], uint32_t addr) {
    asm volatile("ldmatrix.sync.aligned.m8n8.x4.shared.b16 {%0,%1,%2,%3}, [%4];"
                 : "=r"(r[0]), "=r"(r[1]), "=r"(r[2]), "=r"(r[3]) : "r"(addr));
}
__device__ __forceinline__ void ldm_x4t(uint32_t (&r)[4], uint32_t addr) {
    asm volatile("ldmatrix.sync.aligned.m8n8.x4.trans.shared.b16 {%0,%1,%2,%3}, [%4];"
                 : "=r"(r[0]), "=r"(r[1]), "=r"(r[2]), "=r"(r[3]) : "r"(addr));
}
__device__ __forceinline__ void mma_bf16(float (&d)[4], const uint32_t (&a)[4],
                                         uint32_t b0, uint32_t b1) {
    asm volatile("mma.sync.aligned.m16n8k16.row.col.f32.bf16.bf16.f32 "
                 "{%0,%1,%2,%3}, {%4,%5,%6,%7}, {%8,%9}, {%0,%1,%2,%3};"
                 : "+f"(d[0]), "+f"(d[1]), "+f"(d[2]), "+f"(d[3])
                 : "r"(a[0]), "r"(a[1]), "r"(a[2]), "r"(a[3]), "r"(b0), "r"(b1));
}
#define PBAR(id) asm volatile("bar.sync %0, 64;" :: "r"((id) + 1) : "memory")

// ---------------------------------------------------------------------------
// CSR build (once per launch)
// ---------------------------------------------------------------------------
__global__ void zero_off_k() {
    int i = blockIdx.x * 256 + threadIdx.x;
    if (i <= NN) g_off[i] = 0;
}
__global__ void hist_k(const int* __restrict__ dst) {
    int e = blockIdx.x * 256 + threadIdx.x;
    if (e < NE) atomicAdd(&g_off[__ldg(&dst[e]) + 1], 1);
}
__global__ void scanA_k() {
    __shared__ int wsum[32];
    const int tid  = threadIdx.x;
    const int lane = tid & 31;
    const int wid  = tid >> 5;
    int i = blockIdx.x * SCAN_BLK + tid;
    int c = (i < NN) ? g_off[i + 1] : 0;
    int v = c;
    #pragma unroll
    for (int d = 1; d < 32; d <<= 1) {
        int t = __shfl_up_sync(0xFFFFFFFFu, v, d);
        if (lane >= d) v += t;
    }
    if (lane == 31) wsum[wid] = v;
    __syncthreads();
    if (wid == 0) {
        int w = wsum[lane];
        #pragma unroll
        for (int d = 1; d < 32; d <<= 1) {
            int t = __shfl_up_sync(0xFFFFFFFFu, w, d);
            if (lane >= d) w += t;
        }
        wsum[lane] = w;
    }
    __syncthreads();
    int inc = v + (wid > 0 ? wsum[wid - 1] : 0);
    if (i < NN) {
        g_off[i + 1] = inc;
        g_cur[i] = c;
    }
    if (tid == SCAN_BLK - 1) g_bsum[blockIdx.x] = inc;
}
__global__ void scanB_k() {
    __shared__ int s[64];
    int t = threadIdx.x;
    int v = (t < SCAN_NB) ? g_bsum[t] : 0;
    int lane = t & 31, wid = t >> 5;
    int x = v;
    #pragma unroll
    for (int d = 1; d < 32; d <<= 1) {
        int u = __shfl_up_sync(0xFFFFFFFFu, x, d);
        if (lane >= d) x += u;
    }
    if (lane == 31) s[wid] = x;
    __syncthreads();
    int inc = x + (wid > 0 ? s[0] : 0);
    if (t < SCAN_NB) g_bsum[t] = inc;
}
__global__ void scanC_k() {
    int i = blockIdx.x * SCAN_BLK + threadIdx.x;
    if (i >= NN) return;
    int add = (blockIdx.x > 0) ? g_bsum[blockIdx.x - 1] : 0;
    int inc = g_off[i + 1] + add;
    g_off[i + 1] = inc;
    g_cur[i] = inc - g_cur[i];
}
__global__ void fill_k(const int* __restrict__ src, const int* __restrict__ dst) {
    int e = blockIdx.x * 256 + threadIdx.x;
    if (e >= NE) return;
    int p = atomicAdd(&g_cur[__ldg(&dst[e])], 1);
    g_csr[p] = __ldg(&src[e]);
}

// ---------------------------------------------------------------------------
// Aggregation: pooled[d] = (1+eps)*h[d] + sum h[src]; warp per node, 8-unrolled
// ---------------------------------------------------------------------------
__global__ void agg_k(const float* __restrict__ h,
                      const float* __restrict__ eps, int l) {
    int gt   = blockIdx.x * 256 + threadIdx.x;
    int node = gt >> 5;
    int lane = gt & 31;
    if (node >= NN) return;
    float e = 1.0f + __ldg(&eps[l]);
    float4 acc = __ldg(((const float4*)h) + (size_t)node * 32 + lane);
    acc.x *= e; acc.y *= e; acc.z *= e; acc.w *= e;
    int beg = g_off[node], end = g_off[node + 1];
    int j = beg;
    for (; j + 8 <= end; j += 8) {
        int s[8];
        #pragma unroll
        for (int q = 0; q < 8; q++) s[q] = __ldg(&g_csr[j + q]);
        float4 v[8];
        #pragma unroll
        for (int q = 0; q < 8; q++) v[q] = __ldg(((const float4*)h) + (size_t)s[q] * 32 + lane);
        #pragma unroll
        for (int q = 0; q < 8; q++) {
            acc.x += v[q].x; acc.y += v[q].y; acc.z += v[q].z; acc.w += v[q].w;
        }
    }
    for (; j < end; j++) {
        int s0 = __ldg(&g_csr[j]);
        float4 v0 = __ldg(((const float4*)h) + (size_t)s0 * 32 + lane);
        acc.x += v0.x; acc.y += v0.y; acc.z += v0.z; acc.w += v0.w;
    }
    ((float4*)g_pooled)[(size_t)node * 32 + lane] = acc;
}

// ---------------------------------------------------------------------------
// Weight prep
// ---------------------------------------------------------------------------
__global__ void prep_w_k(const float* __restrict__ W1, const float* __restrict__ W2) {
    int l   = blockIdx.x >> 1;
    int mat = blockIdx.x & 1;
    const float* W = (mat ? W2 : W1) + (size_t)l * 16384;
    __nv_bfloat16* dh = g_wb + ((size_t)(l * 2 + mat) * 2 + 0) * 16384;
    __nv_bfloat16* dl = g_wb + ((size_t)(l * 2 + mat) * 2 + 1) * 16384;
    for (int i = threadIdx.x; i < 16384; i += 256) {
        uint16_t hb, lb;
        split_bf(__ldg(&W[i]), hb, lb);
        dh[i] = __ushort_as_bfloat16(hb);
        dl[i] = __ushort_as_bfloat16(lb);
    }
}

// ---------------------------------------------------------------------------
// Tensor-core fused MLP: 256 threads, 8 warps (4M x 2N, warp tile 32x64),
// 4 pair pipelines on named barriers. 3 split terms fused per k-step.
// ---------------------------------------------------------------------------
#define LDB     272
#define MATSZ   (128 * LDB)
#define AH_OFF  0
#define AL_OFF  MATSZ
#define W1H_OFF (2 * MATSZ)
#define W1L_OFF (3 * MATSZ)
#define W2H_OFF (4 * MATSZ)
#define W2L_OFF (5 * MATSZ)
#define PB1_OFF (6 * MATSZ)
#define PS_OFF  (PB1_OFF + 512)
#define PT_OFF  (PS_OFF + 512)
#define SMEM_REQ (PT_OFF + 512)

__device__ __forceinline__ void gemm_fused(uint32_t sbase,
                                           uint32_t whOff, uint32_t wlOff,
                                           int wm, int wn, int lane,
                                           float acc[2][8][4]) {
    const int lane15 = lane & 15;
    const int lhalf  = (lane >> 4) << 3;
    const uint32_t aRowBase = (uint32_t)(wm * 32 + lane15) * LDB + (uint32_t)lhalf * 2;
    const uint32_t bBaseOff = (uint32_t)lane15 * LDB + (uint32_t)(wn * 64 + lhalf) * 2;
    const uint32_t aH = sbase + AH_OFF + aRowBase;
    const uint32_t aL = sbase + AL_OFF + aRowBase;
    const uint32_t bH = sbase + whOff + bBaseOff;
    const uint32_t bL = sbase + wlOff + bBaseOff;
    #pragma unroll
    for (int ks = 0; ks < 8; ks++) {
        uint32_t aH0[4], aH1[4], aL0[4], aL1[4];
        ldm_x4(aH0, aH + ks * 32);
        ldm_x4(aH1, aH + 16 * LDB + ks * 32);
        ldm_x4(aL0, aL + ks * 32);
        ldm_x4(aL1, aL + 16 * LDB + ks * 32);
        uint32_t bh[4][4], bl[4][4];
        #pragma unroll
        for (int np = 0; np < 4; np++) {
            ldm_x4t(bh[np], bH + (uint32_t)ks * (16 * LDB) + np * 32);
            ldm_x4t(bl[np], bL + (uint32_t)ks * (16 * LDB) + np * 32);
        }
        #pragma unroll
        for (int nt = 0; nt < 8; nt++) {
            uint32_t b0h = bh[nt >> 1][(nt & 1) * 2], b1h = bh[nt >> 1][(nt & 1) * 2 + 1];
            uint32_t b0l = bl[nt >> 1][(nt & 1) * 2], b1l = bl[nt >> 1][(nt & 1) * 2 + 1];
            mma_bf16(acc[0][nt], aH0, b0h, b1h);
            mma_bf16(acc[1][nt], aH1, b0h, b1h);
            mma_bf16(acc[0][nt], aH0, b0l, b1l);
            mma_bf16(acc[1][nt], aH1, b0l, b1l);
            mma_bf16(acc[0][nt], aL0, b0h, b1h);
            mma_bf16(acc[1][nt], aL1, b0h, b1h);
        }
    }
}

__global__ void __launch_bounds__(256, 1) mlp_mma_k(
    float* __restrict__ out, int layer,
    const float* __restrict__ b1, const float* __restrict__ b2,
    const float* __restrict__ gamma, const float* __restrict__ beta,
    const float* __restrict__ bmean, const float* __restrict__ bvar)
{
    extern __shared__ char sm[];
    const uint32_t sbase = smem_u32(sm);
    const int tid  = threadIdx.x;
    const int wid  = tid >> 5;
    const int lane = tid & 31;
    const int wm   = wid & 3;       // 4 M-groups of 32 rows
    const int wn   = wid >> 2;      // 2 N-groups of 64 cols
    const int ptid = (wn << 5) | lane;   // 0..63 within pair

    float* B1f = (float*)(sm + PB1_OFF);
    float* Sf  = (float*)(sm + PS_OFF);
    float* Tf  = (float*)(sm + PT_OFF);
    if (tid < 128) {
        float s = __ldg(&gamma[tid]) * rsqrtf(__ldg(&bvar[tid]) + BN_EPS);
        Sf[tid]  = s;
        Tf[tid]  = __ldg(&b2[tid]) * s + __ldg(&beta[tid]) - __ldg(&bmean[tid]) * s;
        B1f[tid] = __ldg(&b1[tid]);
    }

    {
        const uint4* wsrc = (const uint4*)(g_wb + (size_t)layer * 4 * 16384);
        #pragma unroll
        for (int it = 0; it < 32; it++) {
            int idx = tid + it * 256;
            int mat = idx >> 11;
            int j   = idx & 2047;
            int k   = j >> 4, c = j & 15;
            *(uint4*)(sm + W1H_OFF + mat * MATSZ + k * LDB + c * 16) = __ldg(&wsrc[idx]);
        }
    }
    __syncthreads();

    const int rEp = lane >> 2;
    const int cEp = (lane & 3) * 2;

    for (int t = blockIdx.x; t < NTILES; t += gridDim.x) {
        const int rowBase = t * 128;

        // ---- pair loads + splits its 32 rows ----
        #pragma unroll
        for (int i = 0; i < 16; i++) {
            int idx = ptid + i * 64;               // 0..1023
            int ar = wm * 32 + (idx >> 5), c4 = idx & 31;
            int gr = rowBase + ar;
            float4 v = make_float4(0.f, 0.f, 0.f, 0.f);
            if (gr < NN) v = __ldg(((const float4*)g_pooled) + (size_t)gr * 32 + c4);
            uint32_t h0, l0, h1, l1;
            split2(v.x, v.y, h0, l0);
            split2(v.z, v.w, h1, l1);
            uint32_t off = (uint32_t)ar * LDB + (uint32_t)c4 * 8;
            *(uint2*)(sm + AH_OFF + off) = make_uint2(h0, h1);
            *(uint2*)(sm + AL_OFF + off) = make_uint2(l0, l1);
        }
        PBAR(wm);

        float acc[2][8][4];
        #pragma unroll
        for (int a = 0; a < 2; a++)
            #pragma unroll
            for (int b = 0; b < 8; b++)
                #pragma unroll
                for (int c = 0; c < 4; c++) acc[a][b][c] = 0.f;

        gemm_fused(sbase, W1H_OFF, W1L_OFF, wm, wn, lane, acc);
        PBAR(wm);   // pair done reading A rows

        // ---- epilogue 1: Z = relu(D1 + b1) -> split back into AH/AL ----
        #pragma unroll
        for (int mt = 0; mt < 2; mt++) {
            #pragma unroll
            for (int nt = 0; nt < 8; nt++) {
                int row = wm * 32 + mt * 16 + rEp;
                int col = wn * 64 + nt * 8 + cEp;
                float f0 = fmaxf(acc[mt][nt][0] + B1f[col],     0.f);
                float f1 = fmaxf(acc[mt][nt][1] + B1f[col + 1], 0.f);
                float f2 = fmaxf(acc[mt][nt][2] + B1f[col],     0.f);
                float f3 = fmaxf(acc[mt][nt][3] + B1f[col + 1], 0.f);
                uint32_t h0, l0, h1, l1;
                split2(f0, f1, h0, l0);
                split2(f2, f3, h1, l1);
                uint32_t o0 = (uint32_t)row * LDB + (uint32_t)col * 2;
                uint32_t o1 = o0 + 8 * LDB;
                *(uint32_t*)(sm + AH_OFF + o0) = h0;
                *(uint32_t*)(sm + AL_OFF + o0) = l0;
                *(uint32_t*)(sm + AH_OFF + o1) = h1;
                *(uint32_t*)(sm + AL_OFF + o1) = l1;
            }
        }
        PBAR(wm);

        #pragma unroll
        for (int a = 0; a < 2; a++)
            #pragma unroll
            for (int b = 0; b < 8; b++)
                #pragma unroll
                for (int c = 0; c < 4; c++) acc[a][b][c] = 0.f;

        gemm_fused(sbase, W2H_OFF, W2L_OFF, wm, wn, lane, acc);
        PBAR(wm);   // pair done reading Z before next-tile A write

        // ---- epilogue 2: out = relu(D2 * S + T) ----
        #pragma unroll
        for (int mt = 0; mt < 2; mt++) {
            #pragma unroll
            for (int nt = 0; nt < 8; nt++) {
                int row = wm * 32 + mt * 16 + rEp;
                int col = wn * 64 + nt * 8 + cEp;
                int gr0 = rowBase + row;
                int gr1 = gr0 + 8;
                float2 o0, o1;
                o0.x = fmaxf(fmaf(acc[mt][nt][0], Sf[col],     Tf[col]),     0.f);
                o0.y = fmaxf(fmaf(acc[mt][nt][1], Sf[col + 1], Tf[col + 1]), 0.f);
                o1.x = fmaxf(fmaf(acc[mt][nt][2], Sf[col],     Tf[col]),     0.f);
                o1.y = fmaxf(fmaf(acc[mt][nt][3], Sf[col + 1], Tf[col + 1]), 0.f);
                if (gr0 < NN) *(float2*)(out + (size_t)gr0 * D + col) = o0;
                if (gr1 < NN) *(float2*)(out + (size_t)gr1 * D + col) = o1;
            }
        }
    }
}

// ---------------------------------------------------------------------------
extern "C" void kernel_launch(void* const* d_in, const int* in_sizes, int n_in,
                              void* d_out, int out_size) {
    const float* x     = (const float*)d_in[0];
    const int*   esrc  = (const int*)  d_in[1];
    const int*   edst  = (const int*)  d_in[2];
    const float* eps   = (const float*)d_in[3];
    const float* W1    = (const float*)d_in[4];
    const float* b1    = (const float*)d_in[5];
    const float* W2    = (const float*)d_in[6];
    const float* b2    = (const float*)d_in[7];
    const float* gamma = (const float*)d_in[8];
    const float* beta  = (const float*)d_in[9];
    const float* bmean = (const float*)d_in[10];
    const float* bvar  = (const float*)d_in[11];
    float* out = (float*)d_out;

    static int smem_set = 0;
    if (!smem_set) {
        cudaFuncSetAttribute(mlp_mma_k, cudaFuncAttributeMaxDynamicSharedMemorySize, SMEM_REQ);
        smem_set = 1;
    }

    // hidden_rep[0] = x
    cudaMemcpyAsync(out, x, (size_t)NN * D * sizeof(float), cudaMemcpyDeviceToDevice);

    // one-shot: weight split + CSR build
    prep_w_k<<<NL * 2, 256>>>(W1, W2);
    zero_off_k<<<(NN + 256) / 256, 256>>>();
    hist_k<<<(NE + 255) / 256, 256>>>(edst);
    scanA_k<<<SCAN_NB, SCAN_BLK>>>();
    scanB_k<<<1, 64>>>();
    scanC_k<<<SCAN_NB, SCAN_BLK>>>();
    fill_k<<<(NE + 255) / 256, 256>>>(esrc, edst);

    const int aggGrid = (NN * 32 + 255) / 256;   // 6250

    for (int l = 0; l < NL; l++) {
        const float* h  = out + (size_t)l * NN * D;
        float*       hn = out + (size_t)(l + 1) * NN * D;
        agg_k<<<aggGrid, 256>>>(h, eps, l);
        mlp_mma_k<<<148, 256, SMEM_REQ>>>(hn, l,
            b1 + (size_t)l * D, b2 + (size_t)l * D,
            gamma + (size_t)l * D, beta + (size_t)l * D,
            bmean + (size_t)l * D, bvar + (size_t)l * D);
    }
}

// round 13
// speedup vs baseline: 6.0441x; 1.0465x over previous
#include <cuda_runtime.h>
#include <cuda_bf16.h>
#include <cuda_fp16.h>
#include <cstdint>
#include <cstddef>

#define NN 50000
#define NE 800000
#define D  128
#define NL 5
#define BN_EPS 1e-3f
#define NTILES ((NN + 127) / 128)   // 391

// ---------------- scratch (no allocs allowed) ----------------
__device__ float g_pooled[NN * D];
__device__ __half g_h16[NN * D];                 // fp16 mirror of current h
__device__ __nv_bfloat16 g_wb[NL * 4 * 16384];   // W1h W1l W2h W2l per layer
__device__ int g_off[NN + 1];
__device__ int g_cur[NN];
__device__ int g_csr[NE];
#define SCAN_BLK 1024
#define SCAN_NB  ((NN + SCAN_BLK - 1) / SCAN_BLK)   // 49
__device__ int g_bsum[SCAN_NB];

// ---------------- helpers ----------------
__device__ __forceinline__ uint32_t smem_u32(const void* p) {
    uint32_t a;
    asm("{ .reg .u64 t; cvta.to.shared.u64 t, %1; cvt.u32.u64 %0, t; }" : "=r"(a) : "l"(p));
    return a;
}
__device__ __forceinline__ void split_bf(float v, uint16_t& h, uint16_t& l) {
    __nv_bfloat16 hb = __float2bfloat16_rn(v);
    float rem = v - __bfloat162float(hb);
    h = __bfloat16_as_ushort(hb);
    l = __bfloat16_as_ushort(__float2bfloat16_rn(rem));
}
// truncation split of a float pair: hi = top16 bits of each, lo = rn-bf16 of remainders
__device__ __forceinline__ void split2(float x, float y, uint32_t& hi, uint32_t& lo) {
    uint32_t xi = __float_as_uint(x), yi = __float_as_uint(y);
    hi = __byte_perm(xi, yi, 0x7632);
    float xr = x - __uint_as_float(xi & 0xFFFF0000u);
    float yr = y - __uint_as_float(yi & 0xFFFF0000u);
    asm("cvt.rn.bf16x2.f32 %0, %1, %2;" : "=r"(lo) : "f"(yr), "f"(xr));
}
__device__ __forceinline__ void ldm_x4(uint32_t (&r)[4], uint32_t addr) {
    asm volatile("ldmatrix.sync.aligned.m8n8.x4.shared.b16 {%0,%1,%2,%3}, [%4];"
                 : "=r"(r[0]), "=r"(r[1]), "=r"(r[2]), "=r"(r[3]) : "r"(addr));
}
__device__ __forceinline__ void ldm_x4t(uint32_t (&r)[4], uint32_t addr) {
    asm volatile("ldmatrix.sync.aligned.m8n8.x4.trans.shared.b16 {%0,%1,%2,%3}, [%4];"
                 : "=r"(r[0]), "=r"(r[1]), "=r"(r[2]), "=r"(r[3]) : "r"(addr));
}
__device__ __forceinline__ void mma_bf16(float (&d)[4], const uint32_t (&a)[4],
                                         uint32_t b0, uint32_t b1) {
    asm volatile("mma.sync.aligned.m16n8k16.row.col.f32.bf16.bf16.f32 "
                 "{%0,%1,%2,%3}, {%4,%5,%6,%7}, {%8,%9}, {%0,%1,%2,%3};"
                 : "+f"(d[0]), "+f"(d[1]), "+f"(d[2]), "+f"(d[3])
                 : "r"(a[0]), "r"(a[1]), "r"(a[2]), "r"(a[3]), "r"(b0), "r"(b1));
}
#define PBAR(id) asm volatile("bar.sync %0, 64;" :: "r"((id) + 1) : "memory")

// ---------------------------------------------------------------------------
// CSR build (once per launch)
// ---------------------------------------------------------------------------
__global__ void zero_off_k() {
    int i = blockIdx.x * 256 + threadIdx.x;
    if (i <= NN) g_off[i] = 0;
}
__global__ void hist_k(const int* __restrict__ dst) {
    int e = blockIdx.x * 256 + threadIdx.x;
    if (e < NE) atomicAdd(&g_off[__ldg(&dst[e]) + 1], 1);
}
__global__ void scanA_k() {
    __shared__ int wsum[32];
    const int tid  = threadIdx.x;
    const int lane = tid & 31;
    const int wid  = tid >> 5;
    int i = blockIdx.x * SCAN_BLK + tid;
    int c = (i < NN) ? g_off[i + 1] : 0;
    int v = c;
    #pragma unroll
    for (int d = 1; d < 32; d <<= 1) {
        int t = __shfl_up_sync(0xFFFFFFFFu, v, d);
        if (lane >= d) v += t;
    }
    if (lane == 31) wsum[wid] = v;
    __syncthreads();
    if (wid == 0) {
        int w = wsum[lane];
        #pragma unroll
        for (int d = 1; d < 32; d <<= 1) {
            int t = __shfl_up_sync(0xFFFFFFFFu, w, d);
            if (lane >= d) w += t;
        }
        wsum[lane] = w;
    }
    __syncthreads();
    int inc = v + (wid > 0 ? wsum[wid - 1] : 0);
    if (i < NN) {
        g_off[i + 1] = inc;
        g_cur[i] = c;
    }
    if (tid == SCAN_BLK - 1) g_bsum[blockIdx.x] = inc;
}
__global__ void scanB_k() {
    __shared__ int s[64];
    int t = threadIdx.x;
    int v = (t < SCAN_NB) ? g_bsum[t] : 0;
    int lane = t & 31, wid = t >> 5;
    int x = v;
    #pragma unroll
    for (int d = 1; d < 32; d <<= 1) {
        int u = __shfl_up_sync(0xFFFFFFFFu, x, d);
        if (lane >= d) x += u;
    }
    if (lane == 31) s[wid] = x;
    __syncthreads();
    int inc = x + (wid > 0 ? s[0] : 0);
    if (t < SCAN_NB) g_bsum[t] = inc;
}
__global__ void scanC_k() {
    int i = blockIdx.x * SCAN_BLK + threadIdx.x;
    if (i >= NN) return;
    int add = (blockIdx.x > 0) ? g_bsum[blockIdx.x - 1] : 0;
    int inc = g_off[i + 1] + add;
    g_off[i + 1] = inc;
    g_cur[i] = inc - g_cur[i];
}
__global__ void fill_k(const int* __restrict__ src, const int* __restrict__ dst) {
    int e = blockIdx.x * 256 + threadIdx.x;
    if (e >= NE) return;
    int p = atomicAdd(&g_cur[__ldg(&dst[e])], 1);
    g_csr[p] = __ldg(&src[e]);
}

// ---------------------------------------------------------------------------
// x -> fp16 mirror (layer 0 gather source)
// ---------------------------------------------------------------------------
__global__ void prep_x16_k(const float* __restrict__ x) {
    int i = blockIdx.x * 256 + threadIdx.x;
    if (i >= NN * D / 4) return;
    float4 v = __ldg(((const float4*)x) + i);
    __half2* p = (__half2*)g_h16;
    p[2 * i]     = __floats2half2_rn(v.x, v.y);
    p[2 * i + 1] = __floats2half2_rn(v.z, v.w);
}

// ---------------------------------------------------------------------------
// Aggregation: pooled[d] = (1+eps)*h[d](fp32) + sum h16[src](fp16->fp32).
// Warp per node; lane owns 4 cols (uint2 = 4 halves per neighbor). 8-unrolled.
// ---------------------------------------------------------------------------
__global__ void agg_k(const float* __restrict__ h,
                      const float* __restrict__ eps, int l) {
    int gt   = blockIdx.x * 256 + threadIdx.x;
    int node = gt >> 5;
    int lane = gt & 31;
    if (node >= NN) return;
    float e = 1.0f + __ldg(&eps[l]);
    float4 acc = __ldg(((const float4*)h) + (size_t)node * 32 + lane);
    acc.x *= e; acc.y *= e; acc.z *= e; acc.w *= e;
    const uint2* h16 = (const uint2*)g_h16;   // row = 32 uint2 (128 halves)
    int beg = g_off[node], end = g_off[node + 1];
    int j = beg;
    for (; j + 8 <= end; j += 8) {
        int s[8];
        #pragma unroll
        for (int q = 0; q < 8; q++) s[q] = __ldg(&g_csr[j + q]);
        uint2 u[8];
        #pragma unroll
        for (int q = 0; q < 8; q++) u[q] = __ldg(h16 + (size_t)s[q] * 32 + lane);
        #pragma unroll
        for (int q = 0; q < 8; q++) {
            float2 a = __half22float2(*(const __half2*)&u[q].x);
            float2 b = __half22float2(*(const __half2*)&u[q].y);
            acc.x += a.x; acc.y += a.y; acc.z += b.x; acc.w += b.y;
        }
    }
    for (; j < end; j++) {
        int s0 = __ldg(&g_csr[j]);
        uint2 u = __ldg(h16 + (size_t)s0 * 32 + lane);
        float2 a = __half22float2(*(const __half2*)&u.x);
        float2 b = __half22float2(*(const __half2*)&u.y);
        acc.x += a.x; acc.y += a.y; acc.z += b.x; acc.w += b.y;
    }
    ((float4*)g_pooled)[(size_t)node * 32 + lane] = acc;
}

// ---------------------------------------------------------------------------
// Weight prep
// ---------------------------------------------------------------------------
__global__ void prep_w_k(const float* __restrict__ W1, const float* __restrict__ W2) {
    int l   = blockIdx.x >> 1;
    int mat = blockIdx.x & 1;
    const float* W = (mat ? W2 : W1) + (size_t)l * 16384;
    __nv_bfloat16* dh = g_wb + ((size_t)(l * 2 + mat) * 2 + 0) * 16384;
    __nv_bfloat16* dl = g_wb + ((size_t)(l * 2 + mat) * 2 + 1) * 16384;
    for (int i = threadIdx.x; i < 16384; i += 256) {
        uint16_t hb, lb;
        split_bf(__ldg(&W[i]), hb, lb);
        dh[i] = __ushort_as_bfloat16(hb);
        dl[i] = __ushort_as_bfloat16(lb);
    }
}

// ---------------------------------------------------------------------------
// Tensor-core fused MLP: 256 threads, 8 warps (4M x 2N, warp tile 32x64),
// 4 pair pipelines on named barriers. 3 split terms fused per k-step.
// Epilogue 2 additionally writes the fp16 mirror for next layer's gather.
// ---------------------------------------------------------------------------
#define LDB     272
#define MATSZ   (128 * LDB)
#define AH_OFF  0
#define AL_OFF  MATSZ
#define W1H_OFF (2 * MATSZ)
#define W1L_OFF (3 * MATSZ)
#define W2H_OFF (4 * MATSZ)
#define W2L_OFF (5 * MATSZ)
#define PB1_OFF (6 * MATSZ)
#define PS_OFF  (PB1_OFF + 512)
#define PT_OFF  (PS_OFF + 512)
#define SMEM_REQ (PT_OFF + 512)

__device__ __forceinline__ void gemm_fused(uint32_t sbase,
                                           uint32_t whOff, uint32_t wlOff,
                                           int wm, int wn, int lane,
                                           float acc[2][8][4]) {
    const int lane15 = lane & 15;
    const int lhalf  = (lane >> 4) << 3;
    const uint32_t aRowBase = (uint32_t)(wm * 32 + lane15) * LDB + (uint32_t)lhalf * 2;
    const uint32_t bBaseOff = (uint32_t)lane15 * LDB + (uint32_t)(wn * 64 + lhalf) * 2;
    const uint32_t aH = sbase + AH_OFF + aRowBase;
    const uint32_t aL = sbase + AL_OFF + aRowBase;
    const uint32_t bH = sbase + whOff + bBaseOff;
    const uint32_t bL = sbase + wlOff + bBaseOff;
    #pragma unroll
    for (int ks = 0; ks < 8; ks++) {
        uint32_t aH0[4], aH1[4], aL0[4], aL1[4];
        ldm_x4(aH0, aH + ks * 32);
        ldm_x4(aH1, aH + 16 * LDB + ks * 32);
        ldm_x4(aL0, aL + ks * 32);
        ldm_x4(aL1, aL + 16 * LDB + ks * 32);
        uint32_t bh[4][4], bl[4][4];
        #pragma unroll
        for (int np = 0; np < 4; np++) {
            ldm_x4t(bh[np], bH + (uint32_t)ks * (16 * LDB) + np * 32);
            ldm_x4t(bl[np], bL + (uint32_t)ks * (16 * LDB) + np * 32);
        }
        #pragma unroll
        for (int nt = 0; nt < 8; nt++) {
            uint32_t b0h = bh[nt >> 1][(nt & 1) * 2], b1h = bh[nt >> 1][(nt & 1) * 2 + 1];
            uint32_t b0l = bl[nt >> 1][(nt & 1) * 2], b1l = bl[nt >> 1][(nt & 1) * 2 + 1];
            mma_bf16(acc[0][nt], aH0, b0h, b1h);
            mma_bf16(acc[1][nt], aH1, b0h, b1h);
            mma_bf16(acc[0][nt], aH0, b0l, b1l);
            mma_bf16(acc[1][nt], aH1, b0l, b1l);
            mma_bf16(acc[0][nt], aL0, b0h, b1h);
            mma_bf16(acc[1][nt], aL1, b0h, b1h);
        }
    }
}

__global__ void __launch_bounds__(256, 1) mlp_mma_k(
    float* __restrict__ out, int layer,
    const float* __restrict__ b1, const float* __restrict__ b2,
    const float* __restrict__ gamma, const float* __restrict__ beta,
    const float* __restrict__ bmean, const float* __restrict__ bvar)
{
    extern __shared__ char sm[];
    const uint32_t sbase = smem_u32(sm);
    const int tid  = threadIdx.x;
    const int wid  = tid >> 5;
    const int lane = tid & 31;
    const int wm   = wid & 3;       // 4 M-groups of 32 rows
    const int wn   = wid >> 2;      // 2 N-groups of 64 cols
    const int ptid = (wn << 5) | lane;   // 0..63 within pair

    float* B1f = (float*)(sm + PB1_OFF);
    float* Sf  = (float*)(sm + PS_OFF);
    float* Tf  = (float*)(sm + PT_OFF);
    if (tid < 128) {
        float s = __ldg(&gamma[tid]) * rsqrtf(__ldg(&bvar[tid]) + BN_EPS);
        Sf[tid]  = s;
        Tf[tid]  = __ldg(&b2[tid]) * s + __ldg(&beta[tid]) - __ldg(&bmean[tid]) * s;
        B1f[tid] = __ldg(&b1[tid]);
    }

    {
        const uint4* wsrc = (const uint4*)(g_wb + (size_t)layer * 4 * 16384);
        #pragma unroll
        for (int it = 0; it < 32; it++) {
            int idx = tid + it * 256;
            int mat = idx >> 11;
            int j   = idx & 2047;
            int k   = j >> 4, c = j & 15;
            *(uint4*)(sm + W1H_OFF + mat * MATSZ + k * LDB + c * 16) = __ldg(&wsrc[idx]);
        }
    }
    __syncthreads();

    const int rEp = lane >> 2;
    const int cEp = (lane & 3) * 2;

    for (int t = blockIdx.x; t < NTILES; t += gridDim.x) {
        const int rowBase = t * 128;

        // ---- pair loads + splits its 32 rows ----
        #pragma unroll
        for (int i = 0; i < 16; i++) {
            int idx = ptid + i * 64;               // 0..1023
            int ar = wm * 32 + (idx >> 5), c4 = idx & 31;
            int gr = rowBase + ar;
            float4 v = make_float4(0.f, 0.f, 0.f, 0.f);
            if (gr < NN) v = __ldg(((const float4*)g_pooled) + (size_t)gr * 32 + c4);
            uint32_t h0, l0, h1, l1;
            split2(v.x, v.y, h0, l0);
            split2(v.z, v.w, h1, l1);
            uint32_t off = (uint32_t)ar * LDB + (uint32_t)c4 * 8;
            *(uint2*)(sm + AH_OFF + off) = make_uint2(h0, h1);
            *(uint2*)(sm + AL_OFF + off) = make_uint2(l0, l1);
        }
        PBAR(wm);

        float acc[2][8][4];
        #pragma unroll
        for (int a = 0; a < 2; a++)
            #pragma unroll
            for (int b = 0; b < 8; b++)
                #pragma unroll
                for (int c = 0; c < 4; c++) acc[a][b][c] = 0.f;

        gemm_fused(sbase, W1H_OFF, W1L_OFF, wm, wn, lane, acc);
        PBAR(wm);   // pair done reading A rows

        // ---- epilogue 1: Z = relu(D1 + b1) -> split back into AH/AL ----
        #pragma unroll
        for (int mt = 0; mt < 2; mt++) {
            #pragma unroll
            for (int nt = 0; nt < 8; nt++) {
                int row = wm * 32 + mt * 16 + rEp;
                int col = wn * 64 + nt * 8 + cEp;
                float f0 = fmaxf(acc[mt][nt][0] + B1f[col],     0.f);
                float f1 = fmaxf(acc[mt][nt][1] + B1f[col + 1], 0.f);
                float f2 = fmaxf(acc[mt][nt][2] + B1f[col],     0.f);
                float f3 = fmaxf(acc[mt][nt][3] + B1f[col + 1], 0.f);
                uint32_t h0, l0, h1, l1;
                split2(f0, f1, h0, l0);
                split2(f2, f3, h1, l1);
                uint32_t o0 = (uint32_t)row * LDB + (uint32_t)col * 2;
                uint32_t o1 = o0 + 8 * LDB;
                *(uint32_t*)(sm + AH_OFF + o0) = h0;
                *(uint32_t*)(sm + AL_OFF + o0) = l0;
                *(uint32_t*)(sm + AH_OFF + o1) = h1;
                *(uint32_t*)(sm + AL_OFF + o1) = l1;
            }
        }
        PBAR(wm);

        #pragma unroll
        for (int a = 0; a < 2; a++)
            #pragma unroll
            for (int b = 0; b < 8; b++)
                #pragma unroll
                for (int c = 0; c < 4; c++) acc[a][b][c] = 0.f;

        gemm_fused(sbase, W2H_OFF, W2L_OFF, wm, wn, lane, acc);
        PBAR(wm);   // pair done reading Z before next-tile A write

        // ---- epilogue 2: out = relu(D2 * S + T); also write fp16 mirror ----
        #pragma unroll
        for (int mt = 0; mt < 2; mt++) {
            #pragma unroll
            for (int nt = 0; nt < 8; nt++) {
                int row = wm * 32 + mt * 16 + rEp;
                int col = wn * 64 + nt * 8 + cEp;
                int gr0 = rowBase + row;
                int gr1 = gr0 + 8;
                float2 o0, o1;
                o0.x = fmaxf(fmaf(acc[mt][nt][0], Sf[col],     Tf[col]),     0.f);
                o0.y = fmaxf(fmaf(acc[mt][nt][1], Sf[col + 1], Tf[col + 1]), 0.f);
                o1.x = fmaxf(fmaf(acc[mt][nt][2], Sf[col],     Tf[col]),     0.f);
                o1.y = fmaxf(fmaf(acc[mt][nt][3], Sf[col + 1], Tf[col + 1]), 0.f);
                if (gr0 < NN) {
                    *(float2*)(out + (size_t)gr0 * D + col) = o0;
                    ((__half2*)g_h16)[(size_t)gr0 * 64 + (col >> 1)] = __floats2half2_rn(o0.x, o0.y);
                }
                if (gr1 < NN) {
                    *(float2*)(out + (size_t)gr1 * D + col) = o1;
                    ((__half2*)g_h16)[(size_t)gr1 * 64 + (col >> 1)] = __floats2half2_rn(o1.x, o1.y);
                }
            }
        }
    }
}

// ---------------------------------------------------------------------------
extern "C" void kernel_launch(void* const* d_in, const int* in_sizes, int n_in,
                              void* d_out, int out_size) {
    const float* x     = (const float*)d_in[0];
    const int*   esrc  = (const int*)  d_in[1];
    const int*   edst  = (const int*)  d_in[2];
    const float* eps   = (const float*)d_in[3];
    const float* W1    = (const float*)d_in[4];
    const float* b1    = (const float*)d_in[5];
    const float* W2    = (const float*)d_in[6];
    const float* b2    = (const float*)d_in[7];
    const float* gamma = (const float*)d_in[8];
    const float* beta  = (const float*)d_in[9];
    const float* bmean = (const float*)d_in[10];
    const float* bvar  = (const float*)d_in[11];
    float* out = (float*)d_out;

    static int smem_set = 0;
    if (!smem_set) {
        cudaFuncSetAttribute(mlp_mma_k, cudaFuncAttributeMaxDynamicSharedMemorySize, SMEM_REQ);
        smem_set = 1;
    }

    // hidden_rep[0] = x
    cudaMemcpyAsync(out, x, (size_t)NN * D * sizeof(float), cudaMemcpyDeviceToDevice);

    // one-shot: fp16 mirror of x, weight split, CSR build
    prep_x16_k<<<(NN * D / 4 + 255) / 256, 256>>>(x);
    prep_w_k<<<NL * 2, 256>>>(W1, W2);
    zero_off_k<<<(NN + 256) / 256, 256>>>();
    hist_k<<<(NE + 255) / 256, 256>>>(edst);
    scanA_k<<<SCAN_NB, SCAN_BLK>>>();
    scanB_k<<<1, 64>>>();
    scanC_k<<<SCAN_NB, SCAN_BLK>>>();
    fill_k<<<(NE + 255) / 256, 256>>>(esrc, edst);

    const int aggGrid = (NN * 32 + 255) / 256;   // 6250

    for (int l = 0; l < NL; l++) {
        const float* h  = out + (size_t)l * NN * D;
        float*       hn = out + (size_t)(l + 1) * NN * D;
        agg_k<<<aggGrid, 256>>>(h, eps, l);
        mlp_mma_k<<<148, 256, SMEM_REQ>>>(hn, l,
            b1 + (size_t)l * D, b2 + (size_t)l * D,
            gamma + (size_t)l * D, beta + (size_t)l * D,
            bmean + (size_t)l * D, bvar + (size_t)l * D);
    }
}

// round 14
// speedup vs baseline: 6.1014x; 1.0095x over previous
#include <cuda_runtime.h>
#include <cuda_bf16.h>
#include <cuda_fp16.h>
#include <cstdint>
#include <cstddef>

#define NN 50000
#define NE 800000
#define D  128
#define NL 5
#define BN_EPS 1e-3f
#define NTILES ((NN + 127) / 128)   // 391

// ---------------- scratch (no allocs allowed) ----------------
__device__ float g_pooled[NN * D];
__device__ __half g_h16[NN * D];                 // fp16 mirror of current h
__device__ __nv_bfloat16 g_wb[NL * 4 * 16384];   // W1h W1l W2h W2l per layer
__device__ int g_off[NN + 1];
__device__ int g_cur[NN];
__device__ int g_csr[NE];
#define SCAN_BLK 1024
#define SCAN_NB  ((NN + SCAN_BLK - 1) / SCAN_BLK)   // 49
__device__ int g_bsum[SCAN_NB];

// ---------------- helpers ----------------
__device__ __forceinline__ uint32_t smem_u32(const void* p) {
    uint32_t a;
    asm("{ .reg .u64 t; cvta.to.shared.u64 t, %1; cvt.u32.u64 %0, t; }" : "=r"(a) : "l"(p));
    return a;
}
__device__ __forceinline__ void split_bf(float v, uint16_t& h, uint16_t& l) {
    __nv_bfloat16 hb = __float2bfloat16_rn(v);
    float rem = v - __bfloat162float(hb);
    h = __bfloat16_as_ushort(hb);
    l = __bfloat16_as_ushort(__float2bfloat16_rn(rem));
}
// truncation split of a float pair: hi = top16 bits of each, lo = rn-bf16 of remainders
__device__ __forceinline__ void split2(float x, float y, uint32_t& hi, uint32_t& lo) {
    uint32_t xi = __float_as_uint(x), yi = __float_as_uint(y);
    hi = __byte_perm(xi, yi, 0x7632);
    float xr = x - __uint_as_float(xi & 0xFFFF0000u);
    float yr = y - __uint_as_float(yi & 0xFFFF0000u);
    asm("cvt.rn.bf16x2.f32 %0, %1, %2;" : "=r"(lo) : "f"(yr), "f"(xr));
}
__device__ __forceinline__ void ldm_x4(uint32_t (&r)[4], uint32_t addr) {
    asm volatile("ldmatrix.sync.aligned.m8n8.x4.shared.b16 {%0,%1,%2,%3}, [%4];"
                 : "=r"(r[0]), "=r"(r[1]), "=r"(r[2]), "=r"(r[3]) : "r"(addr));
}
__device__ __forceinline__ void ldm_x4t(uint32_t (&r)[4], uint32_t addr) {
    asm volatile("ldmatrix.sync.aligned.m8n8.x4.trans.shared.b16 {%0,%1,%2,%3}, [%4];"
                 : "=r"(r[0]), "=r"(r[1]), "=r"(r[2]), "=r"(r[3]) : "r"(addr));
}
__device__ __forceinline__ void mma_bf16(float (&d)[4], const uint32_t (&a)[4],
                                         uint32_t b0, uint32_t b1) {
    asm volatile("mma.sync.aligned.m16n8k16.row.col.f32.bf16.bf16.f32 "
                 "{%0,%1,%2,%3}, {%4,%5,%6,%7}, {%8,%9}, {%0,%1,%2,%3};"
                 : "+f"(d[0]), "+f"(d[1]), "+f"(d[2]), "+f"(d[3])
                 : "r"(a[0]), "r"(a[1]), "r"(a[2]), "r"(a[3]), "r"(b0), "r"(b1));
}
#define PBAR(id) asm volatile("bar.sync %0, 64;" :: "r"((id) + 1) : "memory")

// ---------------------------------------------------------------------------
// CSR build (once per launch)
// ---------------------------------------------------------------------------
__global__ void zero_off_k() {
    int i = blockIdx.x * 256 + threadIdx.x;
    if (i <= NN) g_off[i] = 0;
}
__global__ void hist_k(const int* __restrict__ dst) {
    int e = blockIdx.x * 256 + threadIdx.x;
    if (e < NE) atomicAdd(&g_off[__ldg(&dst[e]) + 1], 1);
}
__global__ void scanA_k() {
    __shared__ int wsum[32];
    const int tid  = threadIdx.x;
    const int lane = tid & 31;
    const int wid  = tid >> 5;
    int i = blockIdx.x * SCAN_BLK + tid;
    int c = (i < NN) ? g_off[i + 1] : 0;
    int v = c;
    #pragma unroll
    for (int d = 1; d < 32; d <<= 1) {
        int t = __shfl_up_sync(0xFFFFFFFFu, v, d);
        if (lane >= d) v += t;
    }
    if (lane == 31) wsum[wid] = v;
    __syncthreads();
    if (wid == 0) {
        int w = wsum[lane];
        #pragma unroll
        for (int d = 1; d < 32; d <<= 1) {
            int t = __shfl_up_sync(0xFFFFFFFFu, w, d);
            if (lane >= d) w += t;
        }
        wsum[lane] = w;
    }
    __syncthreads();
    int inc = v + (wid > 0 ? wsum[wid - 1] : 0);
    if (i < NN) {
        g_off[i + 1] = inc;
        g_cur[i] = c;
    }
    if (tid == SCAN_BLK - 1) g_bsum[blockIdx.x] = inc;
}
__global__ void scanB_k() {
    __shared__ int s[64];
    int t = threadIdx.x;
    int v = (t < SCAN_NB) ? g_bsum[t] : 0;
    int lane = t & 31, wid = t >> 5;
    int x = v;
    #pragma unroll
    for (int d = 1; d < 32; d <<= 1) {
        int u = __shfl_up_sync(0xFFFFFFFFu, x, d);
        if (lane >= d) x += u;
    }
    if (lane == 31) s[wid] = x;
    __syncthreads();
    int inc = x + (wid > 0 ? s[0] : 0);
    if (t < SCAN_NB) g_bsum[t] = inc;
}
__global__ void scanC_k() {
    int i = blockIdx.x * SCAN_BLK + threadIdx.x;
    if (i >= NN) return;
    int add = (blockIdx.x > 0) ? g_bsum[blockIdx.x - 1] : 0;
    int inc = g_off[i + 1] + add;
    g_off[i + 1] = inc;
    g_cur[i] = inc - g_cur[i];
}
__global__ void fill_k(const int* __restrict__ src, const int* __restrict__ dst) {
    int e = blockIdx.x * 256 + threadIdx.x;
    if (e >= NE) return;
    int p = atomicAdd(&g_cur[__ldg(&dst[e])], 1);
    g_csr[p] = __ldg(&src[e]);
}

// ---------------------------------------------------------------------------
// x -> out (hidden_rep[0]) and fp16 mirror, one pass
// ---------------------------------------------------------------------------
__global__ void prep_x_k(const float* __restrict__ x, float* __restrict__ out) {
    int i = blockIdx.x * 256 + threadIdx.x;
    if (i >= NN * D / 4) return;
    float4 v = __ldg(((const float4*)x) + i);
    ((float4*)out)[i] = v;
    __half2* p = (__half2*)g_h16;
    p[2 * i]     = __floats2half2_rn(v.x, v.y);
    p[2 * i + 1] = __floats2half2_rn(v.z, v.w);
}

// ---------------------------------------------------------------------------
// Aggregation: pooled[d] = (1+eps)*h[d](fp32) + sum h16[src](fp16->fp32).
// ---------------------------------------------------------------------------
__global__ void agg_k(const float* __restrict__ h,
                      const float* __restrict__ eps, int l) {
    int gt   = blockIdx.x * 256 + threadIdx.x;
    int node = gt >> 5;
    int lane = gt & 31;
    if (node >= NN) return;
    float e = 1.0f + __ldg(&eps[l]);
    float4 acc = __ldg(((const float4*)h) + (size_t)node * 32 + lane);
    acc.x *= e; acc.y *= e; acc.z *= e; acc.w *= e;
    const uint2* h16 = (const uint2*)g_h16;   // row = 32 uint2 (128 halves)
    int beg = g_off[node], end = g_off[node + 1];
    int j = beg;
    for (; j + 8 <= end; j += 8) {
        int s[8];
        #pragma unroll
        for (int q = 0; q < 8; q++) s[q] = __ldg(&g_csr[j + q]);
        uint2 u[8];
        #pragma unroll
        for (int q = 0; q < 8; q++) u[q] = __ldg(h16 + (size_t)s[q] * 32 + lane);
        #pragma unroll
        for (int q = 0; q < 8; q++) {
            float2 a = __half22float2(*(const __half2*)&u[q].x);
            float2 b = __half22float2(*(const __half2*)&u[q].y);
            acc.x += a.x; acc.y += a.y; acc.z += b.x; acc.w += b.y;
        }
    }
    for (; j < end; j++) {
        int s0 = __ldg(&g_csr[j]);
        uint2 u = __ldg(h16 + (size_t)s0 * 32 + lane);
        float2 a = __half22float2(*(const __half2*)&u.x);
        float2 b = __half22float2(*(const __half2*)&u.y);
        acc.x += a.x; acc.y += a.y; acc.z += b.x; acc.w += b.y;
    }
    ((float4*)g_pooled)[(size_t)node * 32 + lane] = acc;
}

// ---------------------------------------------------------------------------
// Weight prep
// ---------------------------------------------------------------------------
__global__ void prep_w_k(const float* __restrict__ W1, const float* __restrict__ W2) {
    int l   = blockIdx.x >> 1;
    int mat = blockIdx.x & 1;
    const float* W = (mat ? W2 : W1) + (size_t)l * 16384;
    __nv_bfloat16* dh = g_wb + ((size_t)(l * 2 + mat) * 2 + 0) * 16384;
    __nv_bfloat16* dl = g_wb + ((size_t)(l * 2 + mat) * 2 + 1) * 16384;
    for (int i = threadIdx.x; i < 16384; i += 256) {
        uint16_t hb, lb;
        split_bf(__ldg(&W[i]), hb, lb);
        dh[i] = __ushort_as_bfloat16(hb);
        dl[i] = __ushort_as_bfloat16(lb);
    }
}

// ---------------------------------------------------------------------------
// Tensor-core fused MLP: 256 threads, 8 warps (4M x 2N, warp tile 32x64),
// 4 pair pipelines on named barriers. 3 split terms fused per k-step,
// fragments explicitly double-buffered across k-steps.
// ---------------------------------------------------------------------------
#define LDB     272
#define MATSZ   (128 * LDB)
#define AH_OFF  0
#define AL_OFF  MATSZ
#define W1H_OFF (2 * MATSZ)
#define W1L_OFF (3 * MATSZ)
#define W2H_OFF (4 * MATSZ)
#define W2L_OFF (5 * MATSZ)
#define PB1_OFF (6 * MATSZ)
#define PS_OFF  (PB1_OFF + 512)
#define PT_OFF  (PS_OFF + 512)
#define SMEM_REQ (PT_OFF + 512)

struct Frag {
    uint32_t aH0[4], aH1[4], aL0[4], aL1[4];
    uint32_t bh[4][4], bl[4][4];
};

__device__ __forceinline__ void frag_load(Frag& f, uint32_t aH, uint32_t aL,
                                          uint32_t bH, uint32_t bL, int ks) {
    ldm_x4(f.aH0, aH + ks * 32);
    ldm_x4(f.aH1, aH + 16 * LDB + ks * 32);
    ldm_x4(f.aL0, aL + ks * 32);
    ldm_x4(f.aL1, aL + 16 * LDB + ks * 32);
    #pragma unroll
    for (int np = 0; np < 4; np++) {
        ldm_x4t(f.bh[np], bH + (uint32_t)ks * (16 * LDB) + np * 32);
        ldm_x4t(f.bl[np], bL + (uint32_t)ks * (16 * LDB) + np * 32);
    }
}

__device__ __forceinline__ void frag_mma(const Frag& f, float acc[2][8][4]) {
    #pragma unroll
    for (int nt = 0; nt < 8; nt++) {
        uint32_t b0h = f.bh[nt >> 1][(nt & 1) * 2], b1h = f.bh[nt >> 1][(nt & 1) * 2 + 1];
        uint32_t b0l = f.bl[nt >> 1][(nt & 1) * 2], b1l = f.bl[nt >> 1][(nt & 1) * 2 + 1];
        mma_bf16(acc[0][nt], f.aH0, b0h, b1h);
        mma_bf16(acc[1][nt], f.aH1, b0h, b1h);
        mma_bf16(acc[0][nt], f.aH0, b0l, b1l);
        mma_bf16(acc[1][nt], f.aH1, b0l, b1l);
        mma_bf16(acc[0][nt], f.aL0, b0h, b1h);
        mma_bf16(acc[1][nt], f.aL1, b0h, b1h);
    }
}

__device__ __forceinline__ void gemm_fused(uint32_t sbase,
                                           uint32_t whOff, uint32_t wlOff,
                                           int wm, int wn, int lane,
                                           float acc[2][8][4]) {
    const int lane15 = lane & 15;
    const int lhalf  = (lane >> 4) << 3;
    const uint32_t aRowBase = (uint32_t)(wm * 32 + lane15) * LDB + (uint32_t)lhalf * 2;
    const uint32_t bBaseOff = (uint32_t)lane15 * LDB + (uint32_t)(wn * 64 + lhalf) * 2;
    const uint32_t aH = sbase + AH_OFF + aRowBase;
    const uint32_t aL = sbase + AL_OFF + aRowBase;
    const uint32_t bH = sbase + whOff + bBaseOff;
    const uint32_t bL = sbase + wlOff + bBaseOff;

    Frag fr[2];
    frag_load(fr[0], aH, aL, bH, bL, 0);
    #pragma unroll
    for (int ks = 0; ks < 8; ks++) {
        if (ks < 7) frag_load(fr[(ks + 1) & 1], aH, aL, bH, bL, ks + 1);
        frag_mma(fr[ks & 1], acc);
    }
}

__global__ void __launch_bounds__(256, 1) mlp_mma_k(
    float* __restrict__ out, int layer,
    const float* __restrict__ b1, const float* __restrict__ b2,
    const float* __restrict__ gamma, const float* __restrict__ beta,
    const float* __restrict__ bmean, const float* __restrict__ bvar)
{
    extern __shared__ char sm[];
    const uint32_t sbase = smem_u32(sm);
    const int tid  = threadIdx.x;
    const int wid  = tid >> 5;
    const int lane = tid & 31;
    const int wm   = wid & 3;       // 4 M-groups of 32 rows
    const int wn   = wid >> 2;      // 2 N-groups of 64 cols
    const int ptid = (wn << 5) | lane;   // 0..63 within pair

    float* B1f = (float*)(sm + PB1_OFF);
    float* Sf  = (float*)(sm + PS_OFF);
    float* Tf  = (float*)(sm + PT_OFF);
    if (tid < 128) {
        float s = __ldg(&gamma[tid]) * rsqrtf(__ldg(&bvar[tid]) + BN_EPS);
        Sf[tid]  = s;
        Tf[tid]  = __ldg(&b2[tid]) * s + __ldg(&beta[tid]) - __ldg(&bmean[tid]) * s;
        B1f[tid] = __ldg(&b1[tid]);
    }

    {
        const uint4* wsrc = (const uint4*)(g_wb + (size_t)layer * 4 * 16384);
        #pragma unroll
        for (int it = 0; it < 32; it++) {
            int idx = tid + it * 256;
            int mat = idx >> 11;
            int j   = idx & 2047;
            int k   = j >> 4, c = j & 15;
            *(uint4*)(sm + W1H_OFF + mat * MATSZ + k * LDB + c * 16) = __ldg(&wsrc[idx]);
        }
    }
    __syncthreads();

    const int rEp = lane >> 2;
    const int cEp = (lane & 3) * 2;

    for (int t = blockIdx.x; t < NTILES; t += gridDim.x) {
        const int rowBase = t * 128;

        // ---- pair loads + splits its 32 rows ----
        #pragma unroll
        for (int i = 0; i < 16; i++) {
            int idx = ptid + i * 64;               // 0..1023
            int ar = wm * 32 + (idx >> 5), c4 = idx & 31;
            int gr = rowBase + ar;
            float4 v = make_float4(0.f, 0.f, 0.f, 0.f);
            if (gr < NN) v = __ldg(((const float4*)g_pooled) + (size_t)gr * 32 + c4);
            uint32_t h0, l0, h1, l1;
            split2(v.x, v.y, h0, l0);
            split2(v.z, v.w, h1, l1);
            uint32_t off = (uint32_t)ar * LDB + (uint32_t)c4 * 8;
            *(uint2*)(sm + AH_OFF + off) = make_uint2(h0, h1);
            *(uint2*)(sm + AL_OFF + off) = make_uint2(l0, l1);
        }
        PBAR(wm);

        float acc[2][8][4];
        #pragma unroll
        for (int a = 0; a < 2; a++)
            #pragma unroll
            for (int b = 0; b < 8; b++)
                #pragma unroll
                for (int c = 0; c < 4; c++) acc[a][b][c] = 0.f;

        gemm_fused(sbase, W1H_OFF, W1L_OFF, wm, wn, lane, acc);
        PBAR(wm);   // pair done reading A rows

        // ---- epilogue 1: Z = relu(D1 + b1) -> split back into AH/AL ----
        #pragma unroll
        for (int mt = 0; mt < 2; mt++) {
            #pragma unroll
            for (int nt = 0; nt < 8; nt++) {
                int row = wm * 32 + mt * 16 + rEp;
                int col = wn * 64 + nt * 8 + cEp;
                float f0 = fmaxf(acc[mt][nt][0] + B1f[col],     0.f);
                float f1 = fmaxf(acc[mt][nt][1] + B1f[col + 1], 0.f);
                float f2 = fmaxf(acc[mt][nt][2] + B1f[col],     0.f);
                float f3 = fmaxf(acc[mt][nt][3] + B1f[col + 1], 0.f);
                uint32_t h0, l0, h1, l1;
                split2(f0, f1, h0, l0);
                split2(f2, f3, h1, l1);
                uint32_t o0 = (uint32_t)row * LDB + (uint32_t)col * 2;
                uint32_t o1 = o0 + 8 * LDB;
                *(uint32_t*)(sm + AH_OFF + o0) = h0;
                *(uint32_t*)(sm + AL_OFF + o0) = l0;
                *(uint32_t*)(sm + AH_OFF + o1) = h1;
                *(uint32_t*)(sm + AL_OFF + o1) = l1;
            }
        }
        PBAR(wm);

        #pragma unroll
        for (int a = 0; a < 2; a++)
            #pragma unroll
            for (int b = 0; b < 8; b++)
                #pragma unroll
                for (int c = 0; c < 4; c++) acc[a][b][c] = 0.f;

        gemm_fused(sbase, W2H_OFF, W2L_OFF, wm, wn, lane, acc);
        PBAR(wm);   // pair done reading Z before next-tile A write

        // ---- epilogue 2: out = relu(D2 * S + T); also write fp16 mirror ----
        #pragma unroll
        for (int mt = 0; mt < 2; mt++) {
            #pragma unroll
            for (int nt = 0; nt < 8; nt++) {
                int row = wm * 32 + mt * 16 + rEp;
                int col = wn * 64 + nt * 8 + cEp;
                int gr0 = rowBase + row;
                int gr1 = gr0 + 8;
                float2 o0, o1;
                o0.x = fmaxf(fmaf(acc[mt][nt][0], Sf[col],     Tf[col]),     0.f);
                o0.y = fmaxf(fmaf(acc[mt][nt][1], Sf[col + 1], Tf[col + 1]), 0.f);
                o1.x = fmaxf(fmaf(acc[mt][nt][2], Sf[col],     Tf[col]),     0.f);
                o1.y = fmaxf(fmaf(acc[mt][nt][3], Sf[col + 1], Tf[col + 1]), 0.f);
                if (gr0 < NN) {
                    *(float2*)(out + (size_t)gr0 * D + col) = o0;
                    ((__half2*)g_h16)[(size_t)gr0 * 64 + (col >> 1)] = __floats2half2_rn(o0.x, o0.y);
                }
                if (gr1 < NN) {
                    *(float2*)(out + (size_t)gr1 * D + col) = o1;
                    ((__half2*)g_h16)[(size_t)gr1 * 64 + (col >> 1)] = __floats2half2_rn(o1.x, o1.y);
                }
            }
        }
    }
}

// ---------------------------------------------------------------------------
extern "C" void kernel_launch(void* const* d_in, const int* in_sizes, int n_in,
                              void* d_out, int out_size) {
    const float* x     = (const float*)d_in[0];
    const int*   esrc  = (const int*)  d_in[1];
    const int*   edst  = (const int*)  d_in[2];
    const float* eps   = (const float*)d_in[3];
    const float* W1    = (const float*)d_in[4];
    const float* b1    = (const float*)d_in[5];
    const float* W2    = (const float*)d_in[6];
    const float* b2    = (const float*)d_in[7];
    const float* gamma = (const float*)d_in[8];
    const float* beta  = (const float*)d_in[9];
    const float* bmean = (const float*)d_in[10];
    const float* bvar  = (const float*)d_in[11];
    float* out = (float*)d_out;

    static int smem_set = 0;
    if (!smem_set) {
        cudaFuncSetAttribute(mlp_mma_k, cudaFuncAttributeMaxDynamicSharedMemorySize, SMEM_REQ);
        smem_set = 1;
    }

    // hidden_rep[0] = x (+ fp16 mirror), weight split, CSR build
    prep_x_k<<<(NN * D / 4 + 255) / 256, 256>>>(x, out);
    prep_w_k<<<NL * 2, 256>>>(W1, W2);
    zero_off_k<<<(NN + 256) / 256, 256>>>();
    hist_k<<<(NE + 255) / 256, 256>>>(edst);
    scanA_k<<<SCAN_NB, SCAN_BLK>>>();
    scanB_k<<<1, 64>>>();
    scanC_k<<<SCAN_NB, SCAN_BLK>>>();
    fill_k<<<(NE + 255) / 256, 256>>>(esrc, edst);

    const int aggGrid = (NN * 32 + 255) / 256;   // 6250

    for (int l = 0; l < NL; l++) {
        const float* h  = out + (size_t)l * NN * D;
        float*       hn = out + (size_t)(l + 1) * NN * D;
        agg_k<<<aggGrid, 256>>>(h, eps, l);
        mlp_mma_k<<<148, 256, SMEM_REQ>>>(hn, l,
            b1 + (size_t)l * D, b2 + (size_t)l * D,
            gamma + (size_t)l * D, beta + (size_t)l * D,
            bmean + (size_t)l * D, bvar + (size_t)l * D);
    }
}

// round 15
// speedup vs baseline: 6.1081x; 1.0011x over previous
#include <cuda_runtime.h>
#include <cuda_bf16.h>
#include <cuda_fp16.h>
#include <cstdint>
#include <cstddef>

#define NN 50000
#define NE 800000
#define D  128
#define NL 5
#define BN_EPS 1e-3f
#define NTILES ((NN + 127) / 128)   // 391

// ---------------- scratch (no allocs allowed) ----------------
__device__ float g_pooled[NN * D];
__device__ __half g_h16[NN * D];                 // fp16 mirror of current h
__device__ __nv_bfloat16 g_wb[NL * 4 * 16384];   // W1h W1l W2h W2l per layer
__device__ int g_off[NN + 1];
__device__ int g_cur[NN];
__device__ int g_csr[NE];
#define SCAN_BLK 1024
#define SCAN_NB  ((NN + SCAN_BLK - 1) / SCAN_BLK)   // 49
__device__ int g_bsum[SCAN_NB];

// ---------------- helpers ----------------
__device__ __forceinline__ uint32_t smem_u32(const void* p) {
    uint32_t a;
    asm("{ .reg .u64 t; cvta.to.shared.u64 t, %1; cvt.u32.u64 %0, t; }" : "=r"(a) : "l"(p));
    return a;
}
__device__ __forceinline__ void split_bf(float v, uint16_t& h, uint16_t& l) {
    __nv_bfloat16 hb = __float2bfloat16_rn(v);
    float rem = v - __bfloat162float(hb);
    h = __bfloat16_as_ushort(hb);
    l = __bfloat16_as_ushort(__float2bfloat16_rn(rem));
}
// truncation split of a float pair: hi = top16 bits of each, lo = rn-bf16 of remainders
__device__ __forceinline__ void split2(float x, float y, uint32_t& hi, uint32_t& lo) {
    uint32_t xi = __float_as_uint(x), yi = __float_as_uint(y);
    hi = __byte_perm(xi, yi, 0x7632);
    float xr = x - __uint_as_float(xi & 0xFFFF0000u);
    float yr = y - __uint_as_float(yi & 0xFFFF0000u);
    asm("cvt.rn.bf16x2.f32 %0, %1, %2;" : "=r"(lo) : "f"(yr), "f"(xr));
}
__device__ __forceinline__ void ldm_x4(uint32_t (&r)[4], uint32_t addr) {
    asm volatile("ldmatrix.sync.aligned.m8n8.x4.shared.b16 {%0,%1,%2,%3}, [%4];"
                 : "=r"(r[0]), "=r"(r[1]), "=r"(r[2]), "=r"(r[3]) : "r"(addr));
}
__device__ __forceinline__ void ldm_x4t(uint32_t (&r)[4], uint32_t addr) {
    asm volatile("ldmatrix.sync.aligned.m8n8.x4.trans.shared.b16 {%0,%1,%2,%3}, [%4];"
                 : "=r"(r[0]), "=r"(r[1]), "=r"(r[2]), "=r"(r[3]) : "r"(addr));
}
// NOTE: non-volatile — pure register op; lets ptxas schedule/pipeline MMAs.
__device__ __forceinline__ void mma_bf16(float (&d)[4], const uint32_t (&a)[4],
                                         uint32_t b0, uint32_t b1) {
    asm("mma.sync.aligned.m16n8k16.row.col.f32.bf16.bf16.f32 "
        "{%0,%1,%2,%3}, {%4,%5,%6,%7}, {%8,%9}, {%0,%1,%2,%3};"
        : "+f"(d[0]), "+f"(d[1]), "+f"(d[2]), "+f"(d[3])
        : "r"(a[0]), "r"(a[1]), "r"(a[2]), "r"(a[3]), "r"(b0), "r"(b1));
}
#define PBAR(id) asm volatile("bar.sync %0, 64;" :: "r"((id) + 1) : "memory")

// ---------------------------------------------------------------------------
// CSR build (once per launch)
// ---------------------------------------------------------------------------
__global__ void zero_off_k() {
    int i = blockIdx.x * 256 + threadIdx.x;
    if (i <= NN) g_off[i] = 0;
}
__global__ void hist_k(const int* __restrict__ dst) {
    int e = blockIdx.x * 256 + threadIdx.x;
    if (e < NE) atomicAdd(&g_off[__ldg(&dst[e]) + 1], 1);
}
__global__ void scanA_k() {
    __shared__ int wsum[32];
    const int tid  = threadIdx.x;
    const int lane = tid & 31;
    const int wid  = tid >> 5;
    int i = blockIdx.x * SCAN_BLK + tid;
    int c = (i < NN) ? g_off[i + 1] : 0;
    int v = c;
    #pragma unroll
    for (int d = 1; d < 32; d <<= 1) {
        int t = __shfl_up_sync(0xFFFFFFFFu, v, d);
        if (lane >= d) v += t;
    }
    if (lane == 31) wsum[wid] = v;
    __syncthreads();
    if (wid == 0) {
        int w = wsum[lane];
        #pragma unroll
        for (int d = 1; d < 32; d <<= 1) {
            int t = __shfl_up_sync(0xFFFFFFFFu, w, d);
            if (lane >= d) w += t;
        }
        wsum[lane] = w;
    }
    __syncthreads();
    int inc = v + (wid > 0 ? wsum[wid - 1] : 0);
    if (i < NN) {
        g_off[i + 1] = inc;
        g_cur[i] = c;
    }
    if (tid == SCAN_BLK - 1) g_bsum[blockIdx.x] = inc;
}
__global__ void scanB_k() {
    __shared__ int s[64];
    int t = threadIdx.x;
    int v = (t < SCAN_NB) ? g_bsum[t] : 0;
    int lane = t & 31, wid = t >> 5;
    int x = v;
    #pragma unroll
    for (int d = 1; d < 32; d <<= 1) {
        int u = __shfl_up_sync(0xFFFFFFFFu, x, d);
        if (lane >= d) x += u;
    }
    if (lane == 31) s[wid] = x;
    __syncthreads();
    int inc = x + (wid > 0 ? s[0] : 0);
    if (t < SCAN_NB) g_bsum[t] = inc;
}
__global__ void scanC_k() {
    int i = blockIdx.x * SCAN_BLK + threadIdx.x;
    if (i >= NN) return;
    int add = (blockIdx.x > 0) ? g_bsum[blockIdx.x - 1] : 0;
    int inc = g_off[i + 1] + add;
    g_off[i + 1] = inc;
    g_cur[i] = inc - g_cur[i];
}
__global__ void fill_k(const int* __restrict__ src, const int* __restrict__ dst) {
    int e = blockIdx.x * 256 + threadIdx.x;
    if (e >= NE) return;
    int p = atomicAdd(&g_cur[__ldg(&dst[e])], 1);
    g_csr[p] = __ldg(&src[e]);
}

// ---------------------------------------------------------------------------
// x -> out (hidden_rep[0]) and fp16 mirror, one pass
// ---------------------------------------------------------------------------
__global__ void prep_x_k(const float* __restrict__ x, float* __restrict__ out) {
    int i = blockIdx.x * 256 + threadIdx.x;
    if (i >= NN * D / 4) return;
    float4 v = __ldg(((const float4*)x) + i);
    ((float4*)out)[i] = v;
    __half2* p = (__half2*)g_h16;
    p[2 * i]     = __floats2half2_rn(v.x, v.y);
    p[2 * i + 1] = __floats2half2_rn(v.z, v.w);
}

// ---------------------------------------------------------------------------
// Aggregation: pooled[d] = (1+eps)*h[d](fp32) + sum h16[src](fp16->fp32).
// ---------------------------------------------------------------------------
__global__ void agg_k(const float* __restrict__ h,
                      const float* __restrict__ eps, int l) {
    int gt   = blockIdx.x * 256 + threadIdx.x;
    int node = gt >> 5;
    int lane = gt & 31;
    if (node >= NN) return;
    float e = 1.0f + __ldg(&eps[l]);
    float4 acc = __ldg(((const float4*)h) + (size_t)node * 32 + lane);
    acc.x *= e; acc.y *= e; acc.z *= e; acc.w *= e;
    const uint2* h16 = (const uint2*)g_h16;   // row = 32 uint2 (128 halves)
    int beg = g_off[node], end = g_off[node + 1];
    int j = beg;
    for (; j + 8 <= end; j += 8) {
        int s[8];
        #pragma unroll
        for (int q = 0; q < 8; q++) s[q] = __ldg(&g_csr[j + q]);
        uint2 u[8];
        #pragma unroll
        for (int q = 0; q < 8; q++) u[q] = __ldg(h16 + (size_t)s[q] * 32 + lane);
        #pragma unroll
        for (int q = 0; q < 8; q++) {
            float2 a = __half22float2(*(const __half2*)&u[q].x);
            float2 b = __half22float2(*(const __half2*)&u[q].y);
            acc.x += a.x; acc.y += a.y; acc.z += b.x; acc.w += b.y;
        }
    }
    for (; j < end; j++) {
        int s0 = __ldg(&g_csr[j]);
        uint2 u = __ldg(h16 + (size_t)s0 * 32 + lane);
        float2 a = __half22float2(*(const __half2*)&u.x);
        float2 b = __half22float2(*(const __half2*)&u.y);
        acc.x += a.x; acc.y += a.y; acc.z += b.x; acc.w += b.y;
    }
    ((float4*)g_pooled)[(size_t)node * 32 + lane] = acc;
}

// ---------------------------------------------------------------------------
// Weight prep
// ---------------------------------------------------------------------------
__global__ void prep_w_k(const float* __restrict__ W1, const float* __restrict__ W2) {
    int l   = blockIdx.x >> 1;
    int mat = blockIdx.x & 1;
    const float* W = (mat ? W2 : W1) + (size_t)l * 16384;
    __nv_bfloat16* dh = g_wb + ((size_t)(l * 2 + mat) * 2 + 0) * 16384;
    __nv_bfloat16* dl = g_wb + ((size_t)(l * 2 + mat) * 2 + 1) * 16384;
    for (int i = threadIdx.x; i < 16384; i += 256) {
        uint16_t hb, lb;
        split_bf(__ldg(&W[i]), hb, lb);
        dh[i] = __ushort_as_bfloat16(hb);
        dl[i] = __ushort_as_bfloat16(lb);
    }
}

// ---------------------------------------------------------------------------
// Tensor-core fused MLP: 256 threads, 8 warps (4M x 2N, warp tile 32x64),
// 4 pair pipelines on named barriers. 3 split terms fused per k-step,
// fragments double-buffered; MMAs issued term-major so each accumulator's
// RAW distance is 16 MMAs (was 1).
// ---------------------------------------------------------------------------
#define LDB     272
#define MATSZ   (128 * LDB)
#define AH_OFF  0
#define AL_OFF  MATSZ
#define W1H_OFF (2 * MATSZ)
#define W1L_OFF (3 * MATSZ)
#define W2H_OFF (4 * MATSZ)
#define W2L_OFF (5 * MATSZ)
#define PB1_OFF (6 * MATSZ)
#define PS_OFF  (PB1_OFF + 512)
#define PT_OFF  (PS_OFF + 512)
#define SMEM_REQ (PT_OFF + 512)

struct Frag {
    uint32_t aH0[4], aH1[4], aL0[4], aL1[4];
    uint32_t bh[4][4], bl[4][4];
};

__device__ __forceinline__ void frag_load(Frag& f, uint32_t aH, uint32_t aL,
                                          uint32_t bH, uint32_t bL, int ks) {
    ldm_x4(f.aH0, aH + ks * 32);
    ldm_x4(f.aH1, aH + 16 * LDB + ks * 32);
    ldm_x4(f.aL0, aL + ks * 32);
    ldm_x4(f.aL1, aL + 16 * LDB + ks * 32);
    #pragma unroll
    for (int np = 0; np < 4; np++) {
        ldm_x4t(f.bh[np], bH + (uint32_t)ks * (16 * LDB) + np * 32);
        ldm_x4t(f.bl[np], bL + (uint32_t)ks * (16 * LDB) + np * 32);
    }
}

// Term-major MMA issue: pass1 aH*bh, pass2 aH*bl, pass3 aL*bh.
// Each accumulator still receives its 3 terms in the same relative order
// as before (bit-identical fp32 result), but consecutive MMAs now target
// different accumulators.
__device__ __forceinline__ void frag_mma(const Frag& f, float acc[2][8][4]) {
    #pragma unroll
    for (int nt = 0; nt < 8; nt++) {
        uint32_t b0 = f.bh[nt >> 1][(nt & 1) * 2], b1 = f.bh[nt >> 1][(nt & 1) * 2 + 1];
        mma_bf16(acc[0][nt], f.aH0, b0, b1);
        mma_bf16(acc[1][nt], f.aH1, b0, b1);
    }
    #pragma unroll
    for (int nt = 0; nt < 8; nt++) {
        uint32_t b0 = f.bl[nt >> 1][(nt & 1) * 2], b1 = f.bl[nt >> 1][(nt & 1) * 2 + 1];
        mma_bf16(acc[0][nt], f.aH0, b0, b1);
        mma_bf16(acc[1][nt], f.aH1, b0, b1);
    }
    #pragma unroll
    for (int nt = 0; nt < 8; nt++) {
        uint32_t b0 = f.bh[nt >> 1][(nt & 1) * 2], b1 = f.bh[nt >> 1][(nt & 1) * 2 + 1];
        mma_bf16(acc[0][nt], f.aL0, b0, b1);
        mma_bf16(acc[1][nt], f.aL1, b0, b1);
    }
}

__device__ __forceinline__ void gemm_fused(uint32_t sbase,
                                           uint32_t whOff, uint32_t wlOff,
                                           int wm, int wn, int lane,
                                           float acc[2][8][4]) {
    const int lane15 = lane & 15;
    const int lhalf  = (lane >> 4) << 3;
    const uint32_t aRowBase = (uint32_t)(wm * 32 + lane15) * LDB + (uint32_t)lhalf * 2;
    const uint32_t bBaseOff = (uint32_t)lane15 * LDB + (uint32_t)(wn * 64 + lhalf) * 2;
    const uint32_t aH = sbase + AH_OFF + aRowBase;
    const uint32_t aL = sbase + AL_OFF + aRowBase;
    const uint32_t bH = sbase + whOff + bBaseOff;
    const uint32_t bL = sbase + wlOff + bBaseOff;

    Frag fr[2];
    frag_load(fr[0], aH, aL, bH, bL, 0);
    #pragma unroll
    for (int ks = 0; ks < 8; ks++) {
        if (ks < 7) frag_load(fr[(ks + 1) & 1], aH, aL, bH, bL, ks + 1);
        frag_mma(fr[ks & 1], acc);
    }
}

__global__ void __launch_bounds__(256, 1) mlp_mma_k(
    float* __restrict__ out, int layer,
    const float* __restrict__ b1, const float* __restrict__ b2,
    const float* __restrict__ gamma, const float* __restrict__ beta,
    const float* __restrict__ bmean, const float* __restrict__ bvar)
{
    extern __shared__ char sm[];
    const uint32_t sbase = smem_u32(sm);
    const int tid  = threadIdx.x;
    const int wid  = tid >> 5;
    const int lane = tid & 31;
    const int wm   = wid & 3;       // 4 M-groups of 32 rows
    const int wn   = wid >> 2;      // 2 N-groups of 64 cols
    const int ptid = (wn << 5) | lane;   // 0..63 within pair

    float* B1f = (float*)(sm + PB1_OFF);
    float* Sf  = (float*)(sm + PS_OFF);
    float* Tf  = (float*)(sm + PT_OFF);
    if (tid < 128) {
        float s = __ldg(&gamma[tid]) * rsqrtf(__ldg(&bvar[tid]) + BN_EPS);
        Sf[tid]  = s;
        Tf[tid]  = __ldg(&b2[tid]) * s + __ldg(&beta[tid]) - __ldg(&bmean[tid]) * s;
        B1f[tid] = __ldg(&b1[tid]);
    }

    {
        const uint4* wsrc = (const uint4*)(g_wb + (size_t)layer * 4 * 16384);
        #pragma unroll
        for (int it = 0; it < 32; it++) {
            int idx = tid + it * 256;
            int mat = idx >> 11;
            int j   = idx & 2047;
            int k   = j >> 4, c = j & 15;
            *(uint4*)(sm + W1H_OFF + mat * MATSZ + k * LDB + c * 16) = __ldg(&wsrc[idx]);
        }
    }
    __syncthreads();

    const int rEp = lane >> 2;
    const int cEp = (lane & 3) * 2;

    for (int t = blockIdx.x; t < NTILES; t += gridDim.x) {
        const int rowBase = t * 128;

        // ---- pair loads + splits its 32 rows ----
        #pragma unroll
        for (int i = 0; i < 16; i++) {
            int idx = ptid + i * 64;               // 0..1023
            int ar = wm * 32 + (idx >> 5), c4 = idx & 31;
            int gr = rowBase + ar;
            float4 v = make_float4(0.f, 0.f, 0.f, 0.f);
            if (gr < NN) v = __ldg(((const float4*)g_pooled) + (size_t)gr * 32 + c4);
            uint32_t h0, l0, h1, l1;
            split2(v.x, v.y, h0, l0);
            split2(v.z, v.w, h1, l1);
            uint32_t off = (uint32_t)ar * LDB + (uint32_t)c4 * 8;
            *(uint2*)(sm + AH_OFF + off) = make_uint2(h0, h1);
            *(uint2*)(sm + AL_OFF + off) = make_uint2(l0, l1);
        }
        PBAR(wm);

        float acc[2][8][4];
        #pragma unroll
        for (int a = 0; a < 2; a++)
            #pragma unroll
            for (int b = 0; b < 8; b++)
                #pragma unroll
                for (int c = 0; c < 4; c++) acc[a][b][c] = 0.f;

        gemm_fused(sbase, W1H_OFF, W1L_OFF, wm, wn, lane, acc);
        PBAR(wm);   // pair done reading A rows

        // ---- epilogue 1: Z = relu(D1 + b1) -> split back into AH/AL ----
        #pragma unroll
        for (int mt = 0; mt < 2; mt++) {
            #pragma unroll
            for (int nt = 0; nt < 8; nt++) {
                int row = wm * 32 + mt * 16 + rEp;
                int col = wn * 64 + nt * 8 + cEp;
                float f0 = fmaxf(acc[mt][nt][0] + B1f[col],     0.f);
                float f1 = fmaxf(acc[mt][nt][1] + B1f[col + 1], 0.f);
                float f2 = fmaxf(acc[mt][nt][2] + B1f[col],     0.f);
                float f3 = fmaxf(acc[mt][nt][3] + B1f[col + 1], 0.f);
                uint32_t h0, l0, h1, l1;
                split2(f0, f1, h0, l0);
                split2(f2, f3, h1, l1);
                uint32_t o0 = (uint32_t)row * LDB + (uint32_t)col * 2;
                uint32_t o1 = o0 + 8 * LDB;
                *(uint32_t*)(sm + AH_OFF + o0) = h0;
                *(uint32_t*)(sm + AL_OFF + o0) = l0;
                *(uint32_t*)(sm + AH_OFF + o1) = h1;
                *(uint32_t*)(sm + AL_OFF + o1) = l1;
            }
        }
        PBAR(wm);

        #pragma unroll
        for (int a = 0; a < 2; a++)
            #pragma unroll
            for (int b = 0; b < 8; b++)
                #pragma unroll
                for (int c = 0; c < 4; c++) acc[a][b][c] = 0.f;

        gemm_fused(sbase, W2H_OFF, W2L_OFF, wm, wn, lane, acc);
        PBAR(wm);   // pair done reading Z before next-tile A write

        // ---- epilogue 2: out = relu(D2 * S + T); also write fp16 mirror ----
        #pragma unroll
        for (int mt = 0; mt < 2; mt++) {
            #pragma unroll
            for (int nt = 0; nt < 8; nt++) {
                int row = wm * 32 + mt * 16 + rEp;
                int col = wn * 64 + nt * 8 + cEp;
                int gr0 = rowBase + row;
                int gr1 = gr0 + 8;
                float2 o0, o1;
                o0.x = fmaxf(fmaf(acc[mt][nt][0], Sf[col],     Tf[col]),     0.f);
                o0.y = fmaxf(fmaf(acc[mt][nt][1], Sf[col + 1], Tf[col + 1]), 0.f);
                o1.x = fmaxf(fmaf(acc[mt][nt][2], Sf[col],     Tf[col]),     0.f);
                o1.y = fmaxf(fmaf(acc[mt][nt][3], Sf[col + 1], Tf[col + 1]), 0.f);
                if (gr0 < NN) {
                    *(float2*)(out + (size_t)gr0 * D + col) = o0;
                    ((__half2*)g_h16)[(size_t)gr0 * 64 + (col >> 1)] = __floats2half2_rn(o0.x, o0.y);
                }
                if (gr1 < NN) {
                    *(float2*)(out + (size_t)gr1 * D + col) = o1;
                    ((__half2*)g_h16)[(size_t)gr1 * 64 + (col >> 1)] = __floats2half2_rn(o1.x, o1.y);
                }
            }
        }
    }
}

// ---------------------------------------------------------------------------
extern "C" void kernel_launch(void* const* d_in, const int* in_sizes, int n_in,
                              void* d_out, int out_size) {
    const float* x     = (const float*)d_in[0];
    const int*   esrc  = (const int*)  d_in[1];
    const int*   edst  = (const int*)  d_in[2];
    const float* eps   = (const float*)d_in[3];
    const float* W1    = (const float*)d_in[4];
    const float* b1    = (const float*)d_in[5];
    const float* W2    = (const float*)d_in[6];
    const float* b2    = (const float*)d_in[7];
    const float* gamma = (const float*)d_in[8];
    const float* beta  = (const float*)d_in[9];
    const float* bmean = (const float*)d_in[10];
    const float* bvar  = (const float*)d_in[11];
    float* out = (float*)d_out;

    static int smem_set = 0;
    if (!smem_set) {
        cudaFuncSetAttribute(mlp_mma_k, cudaFuncAttributeMaxDynamicSharedMemorySize, SMEM_REQ);
        smem_set = 1;
    }

    // hidden_rep[0] = x (+ fp16 mirror), weight split, CSR build
    prep_x_k<<<(NN * D / 4 + 255) / 256, 256>>>(x, out);
    prep_w_k<<<NL * 2, 256>>>(W1, W2);
    zero_off_k<<<(NN + 256) / 256, 256>>>();
    hist_k<<<(NE + 255) / 256, 256>>>(edst);
    scanA_k<<<SCAN_NB, SCAN_BLK>>>();
    scanB_k<<<1, 64>>>();
    scanC_k<<<SCAN_NB, SCAN_BLK>>>();
    fill_k<<<(NE + 255) / 256, 256>>>(esrc, edst);

    const int aggGrid = (NN * 32 + 255) / 256;   // 6250

    for (int l = 0; l < NL; l++) {
        const float* h  = out + (size_t)l * NN * D;
        float*       hn = out + (size_t)(l + 1) * NN * D;
        agg_k<<<aggGrid, 256>>>(h, eps, l);
        mlp_mma_k<<<148, 256, SMEM_REQ>>>(hn, l,
            b1 + (size_t)l * D, b2 + (size_t)l * D,
            gamma + (size_t)l * D, beta + (size_t)l * D,
            bmean + (size_t)l * D, bvar + (size_t)l * D);
    }
}

// round 17
// speedup vs baseline: 6.8747x; 1.1255x over previous
#include <cuda_runtime.h>
#include <cuda_bf16.h>
#include <cuda_fp16.h>
#include <cstdint>
#include <cstddef>

#define NN 50000
#define NE 800000
#define D  128
#define NL 5
#define BN_EPS 1e-3f
#define NTILES ((NN + 127) / 128)   // 391
#define SC  (1.0f / 256.0f)         // activation range shift (exact power of 2)
#define SCI 256.0f

// ---------------- scratch (no allocs allowed) ----------------
__device__ float g_pooled[NN * D];
__device__ __half g_h16[NN * D];             // fp16 mirror of current h, scaled by SC
__device__ __half g_wb[NL * 4 * 16384];      // W1h W1l W2h W2l per layer (fp16 split)
__device__ int g_off[NN + 1];
__device__ int g_cur[NN];
__device__ int g_csr[NE];
#define SCAN_BLK 1024
#define SCAN_NB  ((NN + SCAN_BLK - 1) / SCAN_BLK)   // 49
__device__ int g_bsum[SCAN_NB];

// ---------------- helpers ----------------
__device__ __forceinline__ uint32_t smem_u32(const void* p) {
    uint32_t a;
    asm("{ .reg .u64 t; cvta.to.shared.u64 t, %1; cvt.u32.u64 %0, t; }" : "=r"(a) : "l"(p));
    return a;
}
__device__ __forceinline__ void ldm_x4(uint32_t (&r)[4], uint32_t addr) {
    asm volatile("ldmatrix.sync.aligned.m8n8.x4.shared.b16 {%0,%1,%2,%3}, [%4];"
                 : "=r"(r[0]), "=r"(r[1]), "=r"(r[2]), "=r"(r[3]) : "r"(addr));
}
__device__ __forceinline__ void ldm_x4t(uint32_t (&r)[4], uint32_t addr) {
    asm volatile("ldmatrix.sync.aligned.m8n8.x4.trans.shared.b16 {%0,%1,%2,%3}, [%4];"
                 : "=r"(r[0]), "=r"(r[1]), "=r"(r[2]), "=r"(r[3]) : "r"(addr));
}
// fp16 inputs, fp32 accumulate
__device__ __forceinline__ void mma_f16(float (&d)[4], const uint32_t (&a)[4],
                                        uint32_t b0, uint32_t b1) {
    asm("mma.sync.aligned.m16n8k16.row.col.f32.f16.f16.f32 "
        "{%0,%1,%2,%3}, {%4,%5,%6,%7}, {%8,%9}, {%0,%1,%2,%3};"
        : "+f"(d[0]), "+f"(d[1]), "+f"(d[2]), "+f"(d[3])
        : "r"(a[0]), "r"(a[1]), "r"(a[2]), "r"(a[3]), "r"(b0), "r"(b1));
}
#define PBAR(id) asm volatile("bar.sync %0, 64;" :: "r"((id) + 1) : "memory")

// ---------------------------------------------------------------------------
// CSR build (once per launch)
// ---------------------------------------------------------------------------
__global__ void zero_off_k() {
    int i = blockIdx.x * 256 + threadIdx.x;
    if (i <= NN) g_off[i] = 0;
}
__global__ void hist_k(const int* __restrict__ dst) {
    int e = blockIdx.x * 256 + threadIdx.x;
    if (e < NE) atomicAdd(&g_off[__ldg(&dst[e]) + 1], 1);
}
__global__ void scanA_k() {
    __shared__ int wsum[32];
    const int tid  = threadIdx.x;
    const int lane = tid & 31;
    const int wid  = tid >> 5;
    int i = blockIdx.x * SCAN_BLK + tid;
    int c = (i < NN) ? g_off[i + 1] : 0;
    int v = c;
    #pragma unroll
    for (int d = 1; d < 32; d <<= 1) {
        int t = __shfl_up_sync(0xFFFFFFFFu, v, d);
        if (lane >= d) v += t;
    }
    if (lane == 31) wsum[wid] = v;
    __syncthreads();
    if (wid == 0) {
        int w = wsum[lane];
        #pragma unroll
        for (int d = 1; d < 32; d <<= 1) {
            int t = __shfl_up_sync(0xFFFFFFFFu, w, d);
            if (lane >= d) w += t;
        }
        wsum[lane] = w;
    }
    __syncthreads();
    int inc = v + (wid > 0 ? wsum[wid - 1] : 0);
    if (i < NN) {
        g_off[i + 1] = inc;
        g_cur[i] = c;
    }
    if (tid == SCAN_BLK - 1) g_bsum[blockIdx.x] = inc;
}
__global__ void scanB_k() {
    __shared__ int s[64];
    int t = threadIdx.x;
    int v = (t < SCAN_NB) ? g_bsum[t] : 0;
    int lane = t & 31, wid = t >> 5;
    int x = v;
    #pragma unroll
    for (int d = 1; d < 32; d <<= 1) {
        int u = __shfl_up_sync(0xFFFFFFFFu, x, d);
        if (lane >= d) x += u;
    }
    if (lane == 31) s[wid] = x;
    __syncthreads();
    int inc = x + (wid > 0 ? s[0] : 0);
    if (t < SCAN_NB) g_bsum[t] = inc;
}
__global__ void scanC_k() {
    int i = blockIdx.x * SCAN_BLK + threadIdx.x;
    if (i >= NN) return;
    int add = (blockIdx.x > 0) ? g_bsum[blockIdx.x - 1] : 0;
    int inc = g_off[i + 1] + add;
    g_off[i + 1] = inc;
    g_cur[i] = inc - g_cur[i];
}
__global__ void fill_k(const int* __restrict__ src, const int* __restrict__ dst) {
    int e = blockIdx.x * 256 + threadIdx.x;
    if (e >= NE) return;
    int p = atomicAdd(&g_cur[__ldg(&dst[e])], 1);
    g_csr[p] = __ldg(&src[e]);
}

// ---------------------------------------------------------------------------
// x -> out (hidden_rep[0]) and scaled fp16 mirror, one pass
// ---------------------------------------------------------------------------
__global__ void prep_x_k(const float* __restrict__ x, float* __restrict__ out) {
    int i = blockIdx.x * 256 + threadIdx.x;
    if (i >= NN * D / 4) return;
    float4 v = __ldg(((const float4*)x) + i);
    ((float4*)out)[i] = v;
    __half2* p = (__half2*)g_h16;
    p[2 * i]     = __floats2half2_rn(v.x * SC, v.y * SC);
    p[2 * i + 1] = __floats2half2_rn(v.z * SC, v.w * SC);
}

// ---------------------------------------------------------------------------
// Aggregation: pooled[d] = (1+eps)*h[d](fp32) + SCI * sum h16[src](scaled fp16).
// ---------------------------------------------------------------------------
__global__ void agg_k(const float* __restrict__ h,
                      const float* __restrict__ eps, int l) {
    int gt   = blockIdx.x * 256 + threadIdx.x;
    int node = gt >> 5;
    int lane = gt & 31;
    if (node >= NN) return;
    float e = 1.0f + __ldg(&eps[l]);
    float4 self = __ldg(((const float4*)h) + (size_t)node * 32 + lane);
    float4 acc = make_float4(0.f, 0.f, 0.f, 0.f);
    const uint2* h16 = (const uint2*)g_h16;   // row = 32 uint2 (128 halves)
    int beg = g_off[node], end = g_off[node + 1];
    int j = beg;
    for (; j + 8 <= end; j += 8) {
        int s[8];
        #pragma unroll
        for (int q = 0; q < 8; q++) s[q] = __ldg(&g_csr[j + q]);
        uint2 u[8];
        #pragma unroll
        for (int q = 0; q < 8; q++) u[q] = __ldg(h16 + (size_t)s[q] * 32 + lane);
        #pragma unroll
        for (int q = 0; q < 8; q++) {
            float2 a = __half22float2(*(const __half2*)&u[q].x);
            float2 b = __half22float2(*(const __half2*)&u[q].y);
            acc.x += a.x; acc.y += a.y; acc.z += b.x; acc.w += b.y;
        }
    }
    for (; j < end; j++) {
        int s0 = __ldg(&g_csr[j]);
        uint2 u = __ldg(h16 + (size_t)s0 * 32 + lane);
        float2 a = __half22float2(*(const __half2*)&u.x);
        float2 b = __half22float2(*(const __half2*)&u.y);
        acc.x += a.x; acc.y += a.y; acc.z += b.x; acc.w += b.y;
    }
    acc.x = fmaf(acc.x, SCI, e * self.x);
    acc.y = fmaf(acc.y, SCI, e * self.y);
    acc.z = fmaf(acc.z, SCI, e * self.z);
    acc.w = fmaf(acc.w, SCI, e * self.w);
    ((float4*)g_pooled)[(size_t)node * 32 + lane] = acc;
}

// ---------------------------------------------------------------------------
// Weight prep: fp32 W -> fp16 hi + fp16 lo (residual), row-major
// ---------------------------------------------------------------------------
__global__ void prep_w_k(const float* __restrict__ W1, const float* __restrict__ W2) {
    int l   = blockIdx.x >> 1;
    int mat = blockIdx.x & 1;
    const float* W = (mat ? W2 : W1) + (size_t)l * 16384;
    __half* dh = g_wb + ((size_t)(l * 2 + mat) * 2 + 0) * 16384;
    __half* dl = g_wb + ((size_t)(l * 2 + mat) * 2 + 1) * 16384;
    for (int i = threadIdx.x; i < 16384; i += 256) {
        float w = __ldg(&W[i]);
        __half hh = __float2half_rn(w);
        dh[i] = hh;
        dl[i] = __float2half_rn(w - __half2float(hh));
    }
}

// ---------------------------------------------------------------------------
// Tensor-core fused MLP: 256 threads, 8 warps (4M x 2N, warp tile 32x64),
// 4 pair pipelines on named barriers. A operand = single fp16 plane carrying
// activations scaled by SC; W split fp16 hi/lo -> 2 MMA terms per k-step.
// relu homogeneity keeps the scale exact: Z*SC = relu(acc + b1*SC);
// final epilogue folds SCI into the BN scale.
// ---------------------------------------------------------------------------
#define LDB     272
#define MATSZ   (128 * LDB)
#define A_OFF   0
#define W1H_OFF (1 * MATSZ)
#define W1L_OFF (2 * MATSZ)
#define W2H_OFF (3 * MATSZ)
#define W2L_OFF (4 * MATSZ)
#define PB1_OFF (5 * MATSZ)
#define PS_OFF  (PB1_OFF + 512)
#define PT_OFF  (PS_OFF + 512)
#define SMEM_REQ (PT_OFF + 512)   // 175616

struct Frag {
    uint32_t a0[4], a1[4];
    uint32_t bh[4][4], bl[4][4];
};

__device__ __forceinline__ void frag_load(Frag& f, uint32_t aB, uint32_t bH,
                                          uint32_t bL, int ks) {
    ldm_x4(f.a0, aB + ks * 32);
    ldm_x4(f.a1, aB + 16 * LDB + ks * 32);
    #pragma unroll
    for (int np = 0; np < 4; np++) {
        ldm_x4t(f.bh[np], bH + (uint32_t)ks * (16 * LDB) + np * 32);
        ldm_x4t(f.bl[np], bL + (uint32_t)ks * (16 * LDB) + np * 32);
    }
}

// 2 terms: A*Wh then A*Wl, term-major (RAW distance 16)
__device__ __forceinline__ void frag_mma(const Frag& f, float acc[2][8][4]) {
    #pragma unroll
    for (int nt = 0; nt < 8; nt++) {
        uint32_t b0 = f.bh[nt >> 1][(nt & 1) * 2], b1 = f.bh[nt >> 1][(nt & 1) * 2 + 1];
        mma_f16(acc[0][nt], f.a0, b0, b1);
        mma_f16(acc[1][nt], f.a1, b0, b1);
    }
    #pragma unroll
    for (int nt = 0; nt < 8; nt++) {
        uint32_t b0 = f.bl[nt >> 1][(nt & 1) * 2], b1 = f.bl[nt >> 1][(nt & 1) * 2 + 1];
        mma_f16(acc[0][nt], f.a0, b0, b1);
        mma_f16(acc[1][nt], f.a1, b0, b1);
    }
}

__device__ __forceinline__ void gemm2t(uint32_t sbase,
                                       uint32_t whOff, uint32_t wlOff,
                                       int wm, int wn, int lane,
                                       float acc[2][8][4]) {
    const int lane15 = lane & 15;
    const int lhalf  = (lane >> 4) << 3;
    const uint32_t aRowBase = (uint32_t)(wm * 32 + lane15) * LDB + (uint32_t)lhalf * 2;
    const uint32_t bBaseOff = (uint32_t)lane15 * LDB + (uint32_t)(wn * 64 + lhalf) * 2;
    const uint32_t aB = sbase + A_OFF + aRowBase;
    const uint32_t bH = sbase + whOff + bBaseOff;
    const uint32_t bL = sbase + wlOff + bBaseOff;

    Frag fr[2];
    frag_load(fr[0], aB, bH, bL, 0);
    #pragma unroll
    for (int ks = 0; ks < 8; ks++) {
        if (ks < 7) frag_load(fr[(ks + 1) & 1], aB, bH, bL, ks + 1);
        frag_mma(fr[ks & 1], acc);
    }
}

__global__ void __launch_bounds__(256, 1) mlp_mma_k(
    float* __restrict__ out, int layer,
    const float* __restrict__ b1, const float* __restrict__ b2,
    const float* __restrict__ gamma, const float* __restrict__ beta,
    const float* __restrict__ bmean, const float* __restrict__ bvar)
{
    extern __shared__ char sm[];
    const uint32_t sbase = smem_u32(sm);
    const int tid  = threadIdx.x;
    const int wid  = tid >> 5;
    const int lane = tid & 31;
    const int wm   = wid & 3;       // 4 M-groups of 32 rows
    const int wn   = wid >> 2;      // 2 N-groups of 64 cols
    const int ptid = (wn << 5) | lane;   // 0..63 within pair

    float* B1f = (float*)(sm + PB1_OFF);   // b1 * SC
    float* Sf  = (float*)(sm + PS_OFF);    // BN scale * SCI
    float* Tf  = (float*)(sm + PT_OFF);
    if (tid < 128) {
        float s = __ldg(&gamma[tid]) * rsqrtf(__ldg(&bvar[tid]) + BN_EPS);
        Sf[tid]  = s * SCI;
        Tf[tid]  = __ldg(&b2[tid]) * s + __ldg(&beta[tid]) - __ldg(&bmean[tid]) * s;
        B1f[tid] = __ldg(&b1[tid]) * SC;
    }

    // stage 4 fp16 weight planes (128KB) into padded smem
    {
        const uint4* wsrc = (const uint4*)(g_wb + (size_t)layer * 4 * 16384);
        #pragma unroll
        for (int it = 0; it < 32; it++) {
            int idx = tid + it * 256;        // 0..8191 uint4
            int mat = idx >> 11;
            int j   = idx & 2047;
            int k   = j >> 4, c = j & 15;
            *(uint4*)(sm + W1H_OFF + mat * MATSZ + k * LDB + c * 16) = __ldg(&wsrc[idx]);
        }
    }
    __syncthreads();

    const int rEp = lane >> 2;
    const int cEp = (lane & 3) * 2;

    for (int t = blockIdx.x; t < NTILES; t += gridDim.x) {
        const int rowBase = t * 128;

        // ---- pair loads + converts its 32 rows to scaled fp16 ----
        #pragma unroll
        for (int i = 0; i < 16; i++) {
            int idx = ptid + i * 64;               // 0..1023
            int ar = wm * 32 + (idx >> 5), c4 = idx & 31;
            int gr = rowBase + ar;
            float4 v = make_float4(0.f, 0.f, 0.f, 0.f);
            if (gr < NN) v = __ldg(((const float4*)g_pooled) + (size_t)gr * 32 + c4);
            __half2 p0 = __floats2half2_rn(v.x * SC, v.y * SC);
            __half2 p1 = __floats2half2_rn(v.z * SC, v.w * SC);
            uint32_t off = (uint32_t)ar * LDB + (uint32_t)c4 * 8;
            *(uint2*)(sm + A_OFF + off) =
                make_uint2(*(uint32_t*)&p0, *(uint32_t*)&p1);
        }
        PBAR(wm);

        float acc[2][8][4];
        #pragma unroll
        for (int a = 0; a < 2; a++)
            #pragma unroll
            for (int b = 0; b < 8; b++)
                #pragma unroll
                for (int c = 0; c < 4; c++) acc[a][b][c] = 0.f;

        gemm2t(sbase, W1H_OFF, W1L_OFF, wm, wn, lane, acc);
        PBAR(wm);   // pair done reading A rows

        // ---- epilogue 1: Z*SC = relu(acc + b1*SC) -> fp16 A plane ----
        #pragma unroll
        for (int mt = 0; mt < 2; mt++) {
            #pragma unroll
            for (int nt = 0; nt < 8; nt++) {
                int row = wm * 32 + mt * 16 + rEp;
                int col = wn * 64 + nt * 8 + cEp;
                float f0 = fmaxf(acc[mt][nt][0] + B1f[col],     0.f);
                float f1 = fmaxf(acc[mt][nt][1] + B1f[col + 1], 0.f);
                float f2 = fmaxf(acc[mt][nt][2] + B1f[col],     0.f);
                float f3 = fmaxf(acc[mt][nt][3] + B1f[col + 1], 0.f);
                __half2 z0 = __floats2half2_rn(f0, f1);
                __half2 z1 = __floats2half2_rn(f2, f3);
                uint32_t o0 = (uint32_t)row * LDB + (uint32_t)col * 2;
                uint32_t o1 = o0 + 8 * LDB;
                *(uint32_t*)(sm + A_OFF + o0) = *(uint32_t*)&z0;
                *(uint32_t*)(sm + A_OFF + o1) = *(uint32_t*)&z1;
            }
        }
        PBAR(wm);

        #pragma unroll
        for (int a = 0; a < 2; a++)
            #pragma unroll
            for (int b = 0; b < 8; b++)
                #pragma unroll
                for (int c = 0; c < 4; c++) acc[a][b][c] = 0.f;

        gemm2t(sbase, W2H_OFF, W2L_OFF, wm, wn, lane, acc);
        PBAR(wm);   // pair done reading Z before next-tile A write

        // ---- epilogue 2: out = relu(acc * (S*SCI) + T); write scaled mirror ----
        #pragma unroll
        for (int mt = 0; mt < 2; mt++) {
            #pragma unroll
            for (int nt = 0; nt < 8; nt++) {
                int row = wm * 32 + mt * 16 + rEp;
                int col = wn * 64 + nt * 8 + cEp;
                int gr0 = rowBase + row;
                int gr1 = gr0 + 8;
                float2 o0, o1;
                o0.x = fmaxf(fmaf(acc[mt][nt][0], Sf[col],     Tf[col]),     0.f);
                o0.y = fmaxf(fmaf(acc[mt][nt][1], Sf[col + 1], Tf[col + 1]), 0.f);
                o1.x = fmaxf(fmaf(acc[mt][nt][2], Sf[col],     Tf[col]),     0.f);
                o1.y = fmaxf(fmaf(acc[mt][nt][3], Sf[col + 1], Tf[col + 1]), 0.f);
                if (gr0 < NN) {
                    *(float2*)(out + (size_t)gr0 * D + col) = o0;
                    ((__half2*)g_h16)[(size_t)gr0 * 64 + (col >> 1)] =
                        __floats2half2_rn(o0.x * SC, o0.y * SC);
                }
                if (gr1 < NN) {
                    *(float2*)(out + (size_t)gr1 * D + col) = o1;
                    ((__half2*)g_h16)[(size_t)gr1 * 64 + (col >> 1)] =
                        __floats2half2_rn(o1.x * SC, o1.y * SC);
                }
            }
        }
    }
}

// ---------------------------------------------------------------------------
extern "C" void kernel_launch(void* const* d_in, const int* in_sizes, int n_in,
                              void* d_out, int out_size) {
    const float* x     = (const float*)d_in[0];
    const int*   esrc  = (const int*)  d_in[1];
    const int*   edst  = (const int*)  d_in[2];
    const float* eps   = (const float*)d_in[3];
    const float* W1    = (const float*)d_in[4];
    const float* b1    = (const float*)d_in[5];
    const float* W2    = (const float*)d_in[6];
    const float* b2    = (const float*)d_in[7];
    const float* gamma = (const float*)d_in[8];
    const float* beta  = (const float*)d_in[9];
    const float* bmean = (const float*)d_in[10];
    const float* bvar  = (const float*)d_in[11];
    float* out = (float*)d_out;

    static int smem_set = 0;
    if (!smem_set) {
        cudaFuncSetAttribute(mlp_mma_k, cudaFuncAttributeMaxDynamicSharedMemorySize, SMEM_REQ);
        smem_set = 1;
    }

    // hidden_rep[0] = x (+ scaled fp16 mirror), weight split, CSR build
    prep_x_k<<<(NN * D / 4 + 255) / 256, 256>>>(x, out);
    prep_w_k<<<NL * 2, 256>>>(W1, W2);
    zero_off_k<<<(NN + 256) / 256, 256>>>();
    hist_k<<<(NE + 255) / 256, 256>>>(edst);
    scanA_k<<<SCAN_NB, SCAN_BLK>>>();
    scanB_k<<<1, 64>>>();
    scanC_k<<<SCAN_NB, SCAN_BLK>>>();
    fill_k<<<(NE + 255) / 256, 256>>>(esrc, edst);

    const int aggGrid = (NN * 32 + 255) / 256;   // 6250

    for (int l = 0; l < NL; l++) {
        const float* h  = out + (size_t)l * NN * D;
        float*       hn = out + (size_t)(l + 1) * NN * D;
        agg_k<<<aggGrid, 256>>>(h, eps, l);
        mlp_mma_k<<<148, 256, SMEM_REQ>>>(hn, l,
            b1 + (size_t)l * D, b2 + (size_t)l * D,
            gamma + (size_t)l * D, beta + (size_t)l * D,
            bmean + (size_t)l * D, bvar + (size_t)l * D);
    }
}